// round 1
// baseline (speedup 1.0000x reference)
#include <cuda_runtime.h>
#include <math.h>

// Problem constants (fixed by the dataset)
#define MAX_E 500000
#define MAX_V 50000
#define EB    64      // edges per block in the edge-GEMM
#define PITCH 68      // padded shared pitch (floats): 16B aligned, low conflict

// Scratch (allocation-free rule: __device__ globals)
__device__ float g_A[(size_t)MAX_E * 256];   // 512 MB: per-edge 16x16 A (scaled, tanh'd)
__device__ float g_b[(size_t)MAX_E * 16];    // 32 MB
__device__ float g_s0[MAX_V * 16];
__device__ float g_s1[MAX_V * 16];

// ---------------------------------------------------------------------------
// Fast tanh: odd Taylor/deg-13 poly, valid to |x|<=0.8 (inputs ~N(0,0.01)),
// tanhf fallback for the (probability ~1e-15) tail.
// ---------------------------------------------------------------------------
__device__ __forceinline__ float tanh_fast(float x) {
    float t = x * x;
    if (t > 0.64f) return tanhf(x);
    float p = 3.5921280e-3f;
    p = fmaf(p, t, -8.8632355e-3f);
    p = fmaf(p, t,  2.1869489e-2f);
    p = fmaf(p, t, -5.3968254e-2f);
    p = fmaf(p, t,  1.3333334e-1f);
    p = fmaf(p, t, -3.3333334e-1f);
    p = fmaf(p, t,  1.0f);
    return x * p;
}

// ---------------------------------------------------------------------------
// Packed f32x2 helpers (full-rate fp32 FMA on Blackwell)
// ---------------------------------------------------------------------------
__device__ __forceinline__ unsigned long long pack2(float a, float b) {
    unsigned long long r;
    asm("mov.b64 %0, {%1, %2};" : "=l"(r) : "f"(a), "f"(b));
    return r;
}
__device__ __forceinline__ void unpack2(unsigned long long v, float& a, float& b) {
    asm("mov.b64 {%0, %1}, %2;" : "=f"(a), "=f"(b) : "l"(v));
}
__device__ __forceinline__ void fma2(unsigned long long& d,
                                     unsigned long long a, unsigned long long b) {
    asm("fma.rn.f32x2 %0, %1, %2, %0;" : "+l"(d) : "l"(a), "l"(b));
}

// ---------------------------------------------------------------------------
// Kernel 1: per-edge A matrix.  [E,256] x [256,256] GEMM with gathered rows,
// tanh + (mu/S)/dg scaling epilogue.  64 edges x 256 cols per block.
// Each thread: 4 cols x 16 edges (as 8 f32x2 pairs) -> 32 fma.rn.f32x2 / k.
// ---------------------------------------------------------------------------
__global__ __launch_bounds__(256, 2)
void k_edgeA(const int* __restrict__ Xn, const int* __restrict__ Xe,
             const int* __restrict__ dg, const float* __restrict__ emb,
             const float* __restrict__ xiw, const float* __restrict__ xib, int E)
{
    extern __shared__ float XsT[];        // [256][PITCH]  X transposed: XsT[k][e]
    __shared__ int   s_node[EB], s_nei[EB];
    __shared__ float s_scale[EB];
    const int tid = threadIdx.x;
    const int e0  = blockIdx.x * EB;

    if (tid < EB) {
        int e = e0 + tid;
        int nd = 0, nn = 0; float sc = 0.f;
        if (e < E) { nd = Xn[e]; nn = Xe[e]; sc = 0.05625f / (float)dg[e]; }
        s_node[tid] = nd; s_nei[tid] = nn; s_scale[tid] = sc;
    }
    __syncthreads();

    // Gather concat(emb[node], emb[nei]) into transposed shared tile.
    // Consecutive tid -> consecutive k of one emb row (coalesced global reads).
    #pragma unroll 4
    for (int i = 0; i < 64; ++i) {
        int idx = tid + (i << 8);
        int e = idx >> 8, k = idx & 255;
        int row = (k < 128) ? s_node[e] : s_nei[e];
        XsT[k * PITCH + e] = __ldg(&emb[(size_t)row * 128 + (k & 127)]);
    }
    __syncthreads();

    const int col4 = (tid & 63) * 4;   // 4 output columns
    const int eb   = (tid >> 6) * 16;  // 16 edges (8 packed pairs)

    unsigned long long acc[8][4];
    #pragma unroll
    for (int p = 0; p < 8; ++p)
        #pragma unroll
        for (int c = 0; c < 4; ++c) acc[p][c] = 0ull;

    #pragma unroll 4
    for (int k = 0; k < 256; ++k) {
        const float4 w = __ldg((const float4*)(xiw + ((size_t)k << 8) + col4));
        unsigned long long wd[4];
        wd[0] = pack2(w.x, w.x); wd[1] = pack2(w.y, w.y);
        wd[2] = pack2(w.z, w.z); wd[3] = pack2(w.w, w.w);
        const ulonglong2* xp = (const ulonglong2*)(XsT + k * PITCH + eb);
        ulonglong2 x0 = xp[0], x1 = xp[1], x2 = xp[2], x3 = xp[3];
        unsigned long long xv[8] = { x0.x, x0.y, x1.x, x1.y,
                                     x2.x, x2.y, x3.x, x3.y };
        #pragma unroll
        for (int p = 0; p < 8; ++p)
            #pragma unroll
            for (int c = 0; c < 4; ++c)
                fma2(acc[p][c], xv[p], wd[c]);
    }

    const float4 bias = __ldg((const float4*)(xib + col4));
    #pragma unroll
    for (int p = 0; p < 8; ++p) {
        int ea = eb + 2 * p;
        float va[4], vb[4];
        unpack2(acc[p][0], va[0], vb[0]);
        unpack2(acc[p][1], va[1], vb[1]);
        unpack2(acc[p][2], va[2], vb[2]);
        unpack2(acc[p][3], va[3], vb[3]);
        if (e0 + ea < E) {
            float s = s_scale[ea];
            float4 o;
            o.x = s * tanh_fast(va[0] + bias.x);
            o.y = s * tanh_fast(va[1] + bias.y);
            o.z = s * tanh_fast(va[2] + bias.z);
            o.w = s * tanh_fast(va[3] + bias.w);
            *(float4*)(g_A + (size_t)(e0 + ea) * 256 + col4) = o;
        }
        if (e0 + ea + 1 < E) {
            float s = s_scale[ea + 1];
            float4 o;
            o.x = s * tanh_fast(vb[0] + bias.x);
            o.y = s * tanh_fast(vb[1] + bias.y);
            o.z = s * tanh_fast(vb[2] + bias.z);
            o.w = s * tanh_fast(vb[3] + bias.w);
            *(float4*)(g_A + (size_t)(e0 + ea + 1) * 256 + col4) = o;
        }
    }
}

// ---------------------------------------------------------------------------
// Kernel 2: b = tanh(emb[src] @ rou_w + rou_b)   (16 threads per edge)
// ---------------------------------------------------------------------------
__global__ __launch_bounds__(256)
void k_edgeb(const int* __restrict__ Xn, const float* __restrict__ emb,
             const float* __restrict__ rw, const float* __restrict__ rb, int E)
{
    __shared__ float rwT[16 * 132];   // transposed rou_w, padded pitch
    const int tid = threadIdx.x;
    for (int idx = tid; idx < 2048; idx += 256) {
        int k = idx >> 4, j = idx & 15;
        rwT[j * 132 + k] = rw[idx];
    }
    __syncthreads();
    int e = blockIdx.x * 16 + (tid >> 4);
    int j = tid & 15;
    if (e >= E) return;
    int node = __ldg(&Xn[e]);
    const float* er = emb + (size_t)node * 128;
    const float* wr = rwT + j * 132;
    float acc = __ldg(&rb[j]);
    #pragma unroll
    for (int k = 0; k < 128; k += 4) {
        float4 xv = __ldg((const float4*)(er + k));
        float4 wv = *(const float4*)(wr + k);
        acc = fmaf(xv.x, wv.x, acc);
        acc = fmaf(xv.y, wv.y, acc);
        acc = fmaf(xv.z, wv.z, acc);
        acc = fmaf(xv.w, wv.w, acc);
    }
    g_b[(size_t)e * 16 + j] = tanh_fast(acc);
}

// ---------------------------------------------------------------------------
// states utilities
// ---------------------------------------------------------------------------
__global__ void k_zero(int sel, int n) {
    float* p = sel ? g_s1 : g_s0;
    int i = blockIdx.x * blockDim.x + threadIdx.x;
    if (i < n) p[i] = 0.f;
}

// Step 1 specialization: states=0 => H = b; just scatter-add b (skips one
// full 512 MB pass over g_A).
__global__ void k_prop_first(const int* __restrict__ Xe, int sel_out, int E) {
    float* out = sel_out ? g_s1 : g_s0;
    int idx = blockIdx.x * blockDim.x + threadIdx.x;
    if (idx >= E * 16) return;
    int e = idx >> 4, i = idx & 15;
    atomicAdd(&out[__ldg(&Xe[e]) * 16 + i], g_b[idx]);
}

// Generic step: H = A_e @ states[src] + b_e, scatter-add to states'[nbr].
// 16 lanes per edge; H broadcast via width-16 shuffles; A streams via LDG.128.
__global__ __launch_bounds__(256)
void k_prop(const int* __restrict__ Xn, const int* __restrict__ Xe,
            int sel_in, int E)
{
    const float* in  = sel_in ? g_s1 : g_s0;
    float*       out = sel_in ? g_s0 : g_s1;
    int idx = blockIdx.x * blockDim.x + threadIdx.x;
    int e = idx >> 4, i = idx & 15;
    if (e >= E) return;  // E*16 is an exact multiple of 256; warp-uniform
    int node = __ldg(&Xn[e]);
    float h = in[node * 16 + i];
    float acc = g_b[(size_t)idx];
    const float4* arow = (const float4*)(g_A + (size_t)e * 256 + i * 16);
    #pragma unroll
    for (int t4 = 0; t4 < 4; ++t4) {
        float4 a = __ldg(arow + t4);
        acc = fmaf(a.x, __shfl_sync(0xffffffffu, h, 4 * t4 + 0, 16), acc);
        acc = fmaf(a.y, __shfl_sync(0xffffffffu, h, 4 * t4 + 1, 16), acc);
        acc = fmaf(a.z, __shfl_sync(0xffffffffu, h, 4 * t4 + 2, 16), acc);
        acc = fmaf(a.w, __shfl_sync(0xffffffffu, h, 4 * t4 + 3, 16), acc);
    }
    atomicAdd(&out[__ldg(&Xe[e]) * 16 + i], acc);
}

// ---------------------------------------------------------------------------
// Readout: logits = concat(emb, states) @ lin_w + lin_b, softmax.  Warp/node.
// ---------------------------------------------------------------------------
__global__ __launch_bounds__(256)
void k_final(const float* __restrict__ emb, const float* __restrict__ lw,
             const float* __restrict__ lb, float* __restrict__ out,
             int sel_states, int V)
{
    const float* st = sel_states ? g_s1 : g_s0;
    int v = (blockIdx.x * blockDim.x + threadIdx.x) >> 5;
    int lane = threadIdx.x & 31;
    if (v >= V) return;
    float p0 = 0.f, p1 = 0.f, p2 = 0.f;
    #pragma unroll
    for (int m = 0; m < 4; ++m) {
        int row = lane + 32 * m;
        float f = __ldg(&emb[(size_t)v * 128 + row]);
        p0 = fmaf(f, __ldg(&lw[row * 3 + 0]), p0);
        p1 = fmaf(f, __ldg(&lw[row * 3 + 1]), p1);
        p2 = fmaf(f, __ldg(&lw[row * 3 + 2]), p2);
    }
    if (lane < 16) {
        float s = st[v * 16 + lane];
        int row = 128 + lane;
        p0 = fmaf(s, __ldg(&lw[row * 3 + 0]), p0);
        p1 = fmaf(s, __ldg(&lw[row * 3 + 1]), p1);
        p2 = fmaf(s, __ldg(&lw[row * 3 + 2]), p2);
    }
    #pragma unroll
    for (int off = 16; off > 0; off >>= 1) {
        p0 += __shfl_xor_sync(0xffffffffu, p0, off);
        p1 += __shfl_xor_sync(0xffffffffu, p1, off);
        p2 += __shfl_xor_sync(0xffffffffu, p2, off);
    }
    if (lane == 0) {
        p0 += __ldg(&lb[0]); p1 += __ldg(&lb[1]); p2 += __ldg(&lb[2]);
        float mx = fmaxf(p0, fmaxf(p1, p2));
        float e0 = expf(p0 - mx), e1 = expf(p1 - mx), e2 = expf(p2 - mx);
        float inv = 1.f / (e0 + e1 + e2);
        out[(size_t)v * 3 + 0] = e0 * inv;
        out[(size_t)v * 3 + 1] = e1 * inv;
        out[(size_t)v * 3 + 2] = e2 * inv;
    }
}

// ---------------------------------------------------------------------------
extern "C" void kernel_launch(void* const* d_in, const int* in_sizes, int n_in,
                              void* d_out, int out_size)
{
    const int*   X_Node = (const int*)  d_in[0];
    const int*   X_Neis = (const int*)  d_in[1];
    const int*   dg     = (const int*)  d_in[2];
    const float* emb    = (const float*)d_in[3];
    const float* xi_w   = (const float*)d_in[4];
    const float* xi_b   = (const float*)d_in[5];
    const float* rou_w  = (const float*)d_in[6];
    const float* rou_b  = (const float*)d_in[7];
    const float* lin_w  = (const float*)d_in[8];
    const float* lin_b  = (const float*)d_in[9];
    float* out = (float*)d_out;
    const int E = in_sizes[0];
    const int V = in_sizes[3] / 128;

    const int smem = 256 * PITCH * 4;   // 69632 B dynamic shared for k_edgeA
    cudaFuncSetAttribute(k_edgeA, cudaFuncAttributeMaxDynamicSharedMemorySize, smem);

    const int nblkA = (E + EB - 1) / EB;
    k_edgeA<<<nblkA, 256, smem>>>(X_Node, X_Neis, dg, emb, xi_w, xi_b, E);
    k_edgeb<<<(E + 15) / 16, 256>>>(X_Node, emb, rou_w, rou_b, E);

    const int nS = V * 16;
    const int zb = (nS + 255) / 256;
    const int pb = (E * 16 + 255) / 256;

    // step 1 (states=0 => H=b): scatter b into s0
    k_zero<<<zb, 256>>>(0, nS);
    k_prop_first<<<pb, 256>>>(X_Neis, 0, E);
    // step 2: s0 -> s1
    k_zero<<<zb, 256>>>(1, nS);
    k_prop<<<pb, 256>>>(X_Node, X_Neis, 0, E);
    // step 3: s1 -> s0
    k_zero<<<zb, 256>>>(0, nS);
    k_prop<<<pb, 256>>>(X_Node, X_Neis, 1, E);

    k_final<<<(V + 7) / 8, 256>>>(emb, lin_w, lin_b, out, 0, V);
}

// round 3
// speedup vs baseline: 3.3422x; 3.3422x over previous
#include <cuda_runtime.h>
#include <math.h>
#include <stdint.h>

// Problem constants (fixed by the dataset)
#define MAX_E 500000
#define MAX_V 50000
#define PITCH 68   // padded shared pitch (floats): 16B aligned

// Scratch (allocation-free rule: __device__ globals)
__device__ float g_A[(size_t)MAX_E * 256];   // 512 MB: per-edge 16x16 A (scaled, tanh'd)
__device__ float g_P[(size_t)MAX_V * 256];   // emb @ W_top + xi_b
__device__ float g_Q[(size_t)MAX_V * 256];   // emb @ W_bot
__device__ float g_R[MAX_V * 16];            // tanh(emb @ rou_w + rou_b)
__device__ float g_s0[MAX_V * 16];
__device__ float g_s1[MAX_V * 16];

// ---------------------------------------------------------------------------
// Fast tanh: odd deg-13 poly for |x|<=0.8 (inputs ~N(0,0.1)); tanhf fallback.
// ---------------------------------------------------------------------------
__device__ __forceinline__ float tanh_fast(float x) {
    float t = x * x;
    if (t > 0.64f) return tanhf(x);
    float p = 3.5921280e-3f;
    p = fmaf(p, t, -8.8632355e-3f);
    p = fmaf(p, t,  2.1869489e-2f);
    p = fmaf(p, t, -5.3968254e-2f);
    p = fmaf(p, t,  1.3333334e-1f);
    p = fmaf(p, t, -3.3333334e-1f);
    p = fmaf(p, t,  1.0f);
    return x * p;
}

// ---------------------------------------------------------------------------
// Packed f32x2 helpers (full-rate fp32 FMA on Blackwell)
// ---------------------------------------------------------------------------
__device__ __forceinline__ unsigned long long pack2(float a, float b) {
    unsigned long long r;
    asm("mov.b64 %0, {%1, %2};" : "=l"(r) : "f"(a), "f"(b));
    return r;
}
__device__ __forceinline__ void unpack2(unsigned long long v, float& a, float& b) {
    asm("mov.b64 {%0, %1}, %2;" : "=f"(a), "=f"(b) : "l"(v));
}
__device__ __forceinline__ void fma2(unsigned long long& d,
                                     unsigned long long a, unsigned long long b) {
    asm("fma.rn.f32x2 %0, %1, %2, %0;" : "+l"(d) : "l"(a), "l"(b));
}

// ---------------------------------------------------------------------------
// Node GEMM: out_half = emb @ xi_w[half*128 : half*128+128, :] (+ xi_b if 0)
//   emb [V,128], xi_w [256,256].  Tile: 64 nodes x 256 cols, K=128.
//   Each thread: 4 cols x 16 nodes (8 f32x2 pairs).  blockIdx.y = half.
// ---------------------------------------------------------------------------
__global__ __launch_bounds__(256, 2)
void k_nodegemm(const float* __restrict__ emb, const float* __restrict__ xiw,
                const float* __restrict__ xib, int V)
{
    __shared__ float XsT[128 * PITCH];    // XsT[k][r] = emb[v0+r][k]
    const int tid  = threadIdx.x;
    const int v0   = blockIdx.x * 64;
    const int half = blockIdx.y;

    // Load 64 emb rows transposed (coalesced over k).
    #pragma unroll 4
    for (int i = 0; i < 32; ++i) {
        int idx = tid + (i << 8);
        int r = idx >> 7, k = idx & 127;
        int v = v0 + r;
        XsT[k * PITCH + r] = (v < V) ? __ldg(&emb[(size_t)v * 128 + k]) : 0.f;
    }
    __syncthreads();

    const int col4 = (tid & 63) * 4;
    const int rb   = (tid >> 6) * 16;

    unsigned long long acc[8][4];
    #pragma unroll
    for (int p = 0; p < 8; ++p)
        #pragma unroll
        for (int c = 0; c < 4; ++c) acc[p][c] = 0ull;

    const float* wbase = xiw + (size_t)(half * 128) * 256;
    #pragma unroll 4
    for (int k = 0; k < 128; ++k) {
        const float4 w = __ldg((const float4*)(wbase + ((size_t)k << 8) + col4));
        unsigned long long wd[4];
        wd[0] = pack2(w.x, w.x); wd[1] = pack2(w.y, w.y);
        wd[2] = pack2(w.z, w.z); wd[3] = pack2(w.w, w.w);
        const ulonglong2* xp = (const ulonglong2*)(XsT + k * PITCH + rb);
        ulonglong2 x0 = xp[0], x1 = xp[1], x2 = xp[2], x3 = xp[3];
        unsigned long long xv[8] = { x0.x, x0.y, x1.x, x1.y,
                                     x2.x, x2.y, x3.x, x3.y };
        #pragma unroll
        for (int p = 0; p < 8; ++p)
            #pragma unroll
            for (int c = 0; c < 4; ++c)
                fma2(acc[p][c], xv[p], wd[c]);
    }

    float4 bias = make_float4(0.f, 0.f, 0.f, 0.f);
    if (half == 0) bias = __ldg((const float4*)(xib + col4));
    float* dst = half ? g_Q : g_P;

    #pragma unroll
    for (int p = 0; p < 8; ++p) {
        int ra = rb + 2 * p;
        float va[4], vb[4];
        unpack2(acc[p][0], va[0], vb[0]);
        unpack2(acc[p][1], va[1], vb[1]);
        unpack2(acc[p][2], va[2], vb[2]);
        unpack2(acc[p][3], va[3], vb[3]);
        if (v0 + ra < V) {
            float4 o = make_float4(va[0] + bias.x, va[1] + bias.y,
                                   va[2] + bias.z, va[3] + bias.w);
            *(float4*)(dst + (size_t)(v0 + ra) * 256 + col4) = o;
        }
        if (v0 + ra + 1 < V) {
            float4 o = make_float4(vb[0] + bias.x, vb[1] + bias.y,
                                   vb[2] + bias.z, vb[3] + bias.w);
            *(float4*)(dst + (size_t)(v0 + ra + 1) * 256 + col4) = o;
        }
    }
}

// ---------------------------------------------------------------------------
// Edge A assembly: A_e = (mu/S)/dg * tanh(P[src] + Q[nbr]).  One float4/thread.
// ---------------------------------------------------------------------------
__global__ __launch_bounds__(256)
void k_edgeA_add(const int* __restrict__ Xn, const int* __restrict__ Xe,
                 const int* __restrict__ dg, int E)
{
    int idx = blockIdx.x * 256 + threadIdx.x;
    if (idx >= E * 64) return;
    int e = idx >> 6, q = (idx & 63) * 4;
    int src = __ldg(&Xn[e]);
    int nbr = __ldg(&Xe[e]);
    float sc = 0.05625f / (float)__ldg(&dg[e]);
    float4 p = __ldg((const float4*)(g_P + (size_t)src * 256 + q));
    float4 r = __ldg((const float4*)(g_Q + (size_t)nbr * 256 + q));
    float4 o;
    o.x = sc * tanh_fast(p.x + r.x);
    o.y = sc * tanh_fast(p.y + r.y);
    o.z = sc * tanh_fast(p.z + r.z);
    o.w = sc * tanh_fast(p.w + r.w);
    *(float4*)(g_A + (size_t)e * 256 + q) = o;
}

// ---------------------------------------------------------------------------
// R = tanh(emb @ rou_w + rou_b)   (16 threads per node)
// ---------------------------------------------------------------------------
__global__ __launch_bounds__(256)
void k_R(const float* __restrict__ emb, const float* __restrict__ rw,
         const float* __restrict__ rb, int V)
{
    __shared__ float rwT[16 * 132];
    const int tid = threadIdx.x;
    for (int idx = tid; idx < 2048; idx += 256) {
        int k = idx >> 4, j = idx & 15;
        rwT[j * 132 + k] = rw[idx];
    }
    __syncthreads();
    int v = blockIdx.x * 16 + (tid >> 4);
    int j = tid & 15;
    if (v >= V) return;
    const float* er = emb + (size_t)v * 128;
    const float* wr = rwT + j * 132;
    float acc = __ldg(&rb[j]);
    #pragma unroll
    for (int k = 0; k < 128; k += 4) {
        float4 xv = __ldg((const float4*)(er + k));
        float4 wv = *(const float4*)(wr + k);
        acc = fmaf(xv.x, wv.x, acc);
        acc = fmaf(xv.y, wv.y, acc);
        acc = fmaf(xv.z, wv.z, acc);
        acc = fmaf(xv.w, wv.w, acc);
    }
    g_R[v * 16 + j] = tanh_fast(acc);
}

// ---------------------------------------------------------------------------
// states utilities
// ---------------------------------------------------------------------------
__global__ void k_zero(int sel, int n) {
    float* p = sel ? g_s1 : g_s0;
    int i = blockIdx.x * blockDim.x + threadIdx.x;
    if (i < n) p[i] = 0.f;
}

// Step 1 (states=0 => H=b=R[src]): scatter-add R[src] to nbr.
__global__ void k_prop_first(const int* __restrict__ Xn, const int* __restrict__ Xe,
                             int sel_out, int E) {
    float* out = sel_out ? g_s1 : g_s0;
    int idx = blockIdx.x * blockDim.x + threadIdx.x;
    if (idx >= E * 16) return;
    int e = idx >> 4, i = idx & 15;
    atomicAdd(&out[__ldg(&Xe[e]) * 16 + i],
              __ldg(&g_R[__ldg(&Xn[e]) * 16 + i]));
}

// Generic step: H = A_e @ states[src] + R[src], scatter-add to states'[nbr].
__global__ __launch_bounds__(256)
void k_prop(const int* __restrict__ Xn, const int* __restrict__ Xe,
            int sel_in, int E)
{
    const float* in  = sel_in ? g_s1 : g_s0;
    float*       out = sel_in ? g_s0 : g_s1;
    int idx = blockIdx.x * blockDim.x + threadIdx.x;
    int e = idx >> 4, i = idx & 15;
    if (e >= E) return;  // E*16 is a multiple of 256; warp-uniform
    int node = __ldg(&Xn[e]);
    float h = in[node * 16 + i];
    float acc = __ldg(&g_R[node * 16 + i]);
    const float4* arow = (const float4*)(g_A + (size_t)e * 256 + i * 16);
    #pragma unroll
    for (int t4 = 0; t4 < 4; ++t4) {
        float4 a = __ldg(arow + t4);
        acc = fmaf(a.x, __shfl_sync(0xffffffffu, h, 4 * t4 + 0, 16), acc);
        acc = fmaf(a.y, __shfl_sync(0xffffffffu, h, 4 * t4 + 1, 16), acc);
        acc = fmaf(a.z, __shfl_sync(0xffffffffu, h, 4 * t4 + 2, 16), acc);
        acc = fmaf(a.w, __shfl_sync(0xffffffffu, h, 4 * t4 + 3, 16), acc);
    }
    atomicAdd(&out[__ldg(&Xe[e]) * 16 + i], acc);
}

// ---------------------------------------------------------------------------
// Readout: logits = concat(emb, states) @ lin_w + lin_b, softmax.  Warp/node.
// ---------------------------------------------------------------------------
__global__ __launch_bounds__(256)
void k_final(const float* __restrict__ emb, const float* __restrict__ lw,
             const float* __restrict__ lb, float* __restrict__ out,
             int sel_states, int V)
{
    const float* st = sel_states ? g_s1 : g_s0;
    int v = (blockIdx.x * blockDim.x + threadIdx.x) >> 5;
    int lane = threadIdx.x & 31;
    if (v >= V) return;
    float p0 = 0.f, p1 = 0.f, p2 = 0.f;
    #pragma unroll
    for (int m = 0; m < 4; ++m) {
        int row = lane + 32 * m;
        float f = __ldg(&emb[(size_t)v * 128 + row]);
        p0 = fmaf(f, __ldg(&lw[row * 3 + 0]), p0);
        p1 = fmaf(f, __ldg(&lw[row * 3 + 1]), p1);
        p2 = fmaf(f, __ldg(&lw[row * 3 + 2]), p2);
    }
    if (lane < 16) {
        float s = st[v * 16 + lane];
        int row = 128 + lane;
        p0 = fmaf(s, __ldg(&lw[row * 3 + 0]), p0);
        p1 = fmaf(s, __ldg(&lw[row * 3 + 1]), p1);
        p2 = fmaf(s, __ldg(&lw[row * 3 + 2]), p2);
    }
    #pragma unroll
    for (int off = 16; off > 0; off >>= 1) {
        p0 += __shfl_xor_sync(0xffffffffu, p0, off);
        p1 += __shfl_xor_sync(0xffffffffu, p1, off);
        p2 += __shfl_xor_sync(0xffffffffu, p2, off);
    }
    if (lane == 0) {
        p0 += __ldg(&lb[0]); p1 += __ldg(&lb[1]); p2 += __ldg(&lb[2]);
        float mx = fmaxf(p0, fmaxf(p1, p2));
        float e0 = expf(p0 - mx), e1 = expf(p1 - mx), e2 = expf(p2 - mx);
        float inv = 1.f / (e0 + e1 + e2);
        out[(size_t)v * 3 + 0] = e0 * inv;
        out[(size_t)v * 3 + 1] = e1 * inv;
        out[(size_t)v * 3 + 2] = e2 * inv;
    }
}

// ---------------------------------------------------------------------------
extern "C" void kernel_launch(void* const* d_in, const int* in_sizes, int n_in,
                              void* d_out, int out_size)
{
    const int*   X_Node = (const int*)  d_in[0];
    const int*   X_Neis = (const int*)  d_in[1];
    const int*   dg     = (const int*)  d_in[2];
    const float* emb    = (const float*)d_in[3];
    const float* xi_w   = (const float*)d_in[4];
    const float* xi_b   = (const float*)d_in[5];
    const float* rou_w  = (const float*)d_in[6];
    const float* rou_b  = (const float*)d_in[7];
    const float* lin_w  = (const float*)d_in[8];
    const float* lin_b  = (const float*)d_in[9];
    float* out = (float*)d_out;
    const int E = in_sizes[0];
    const int V = in_sizes[3] / 128;

    // Node-level precompute: P = emb@W_top + xi_b, Q = emb@W_bot, R table.
    dim3 ggrid((V + 63) / 64, 2);
    k_nodegemm<<<ggrid, 256>>>(emb, xi_w, xi_b, V);
    k_R<<<(V + 15) / 16, 256>>>(emb, rou_w, rou_b, V);

    // Edge A materialization (gather-add-tanh).
    k_edgeA_add<<<(E * 64 + 255) / 256, 256>>>(X_Node, X_Neis, dg, E);

    const int nS = V * 16;
    const int zb = (nS + 255) / 256;
    const int pb = (E * 16 + 255) / 256;

    // step 1 (states=0 => H=R[src]): scatter into s0
    k_zero<<<zb, 256>>>(0, nS);
    k_prop_first<<<pb, 256>>>(X_Node, X_Neis, 0, E);
    // step 2: s0 -> s1
    k_zero<<<zb, 256>>>(1, nS);
    k_prop<<<pb, 256>>>(X_Node, X_Neis, 0, E);
    // step 3: s1 -> s0
    k_zero<<<zb, 256>>>(0, nS);
    k_prop<<<pb, 256>>>(X_Node, X_Neis, 1, E);

    k_final<<<(V + 7) / 8, 256>>>(emb, lin_w, lin_b, out, 0, V);
}

// round 4
// speedup vs baseline: 3.7860x; 1.1328x over previous
#include <cuda_runtime.h>
#include <math.h>
#include <stdint.h>

// Problem constants (fixed by the dataset)
#define MAX_E 500000
#define MAX_V 50000
#define PITCH 68   // padded shared pitch (floats): 16B aligned

// Scratch (allocation-free rule: __device__ globals)
__device__ float g_P[(size_t)MAX_V * 256];   // emb @ W_top + xi_b   (51 MB, L2-resident)
__device__ float g_Q[(size_t)MAX_V * 256];   // emb @ W_bot          (51 MB, L2-resident)
__device__ float g_R[MAX_V * 16];            // tanh(emb @ rou_w + rou_b)
__device__ float g_s0[MAX_V * 16];
__device__ float g_s1[MAX_V * 16];

// ---------------------------------------------------------------------------
// Fast tanh (scalar): odd deg-13 poly for |x|<=0.8; tanhf fallback.
// ---------------------------------------------------------------------------
__device__ __forceinline__ float tanh_fast(float x) {
    float t = x * x;
    if (t > 0.64f) return tanhf(x);
    float p = 3.5921280e-3f;
    p = fmaf(p, t, -8.8632355e-3f);
    p = fmaf(p, t,  2.1869489e-2f);
    p = fmaf(p, t, -5.3968254e-2f);
    p = fmaf(p, t,  1.3333334e-1f);
    p = fmaf(p, t, -3.3333334e-1f);
    p = fmaf(p, t,  1.0f);
    return x * p;
}

// ---------------------------------------------------------------------------
// Packed f32x2 helpers (full-rate fp32 math on Blackwell)
// ---------------------------------------------------------------------------
typedef unsigned long long u64t;
__device__ __forceinline__ u64t pack2(float a, float b) {
    u64t r; asm("mov.b64 %0, {%1, %2};" : "=l"(r) : "f"(a), "f"(b)); return r;
}
__device__ __forceinline__ void unpack2(u64t v, float& a, float& b) {
    asm("mov.b64 {%0, %1}, %2;" : "=f"(a), "=f"(b) : "l"(v));
}
__device__ __forceinline__ void fma2_acc(u64t& d, u64t a, u64t b) {
    asm("fma.rn.f32x2 %0, %1, %2, %0;" : "+l"(d) : "l"(a), "l"(b));
}
__device__ __forceinline__ u64t fma2(u64t a, u64t b, u64t c) {
    u64t d; asm("fma.rn.f32x2 %0, %1, %2, %3;" : "=l"(d) : "l"(a), "l"(b), "l"(c)); return d;
}
__device__ __forceinline__ u64t mul2(u64t a, u64t b) {
    u64t d; asm("mul.rn.f32x2 %0, %1, %2;" : "=l"(d) : "l"(a), "l"(b)); return d;
}

// Packed tanh on a pair; rare out-of-range halves fall back to tanhf.
struct TanhC {
    u64t c6, c5, c4, c3, c2, c1, c0;
    __device__ __forceinline__ void init() {
        c6 = pack2( 3.5921280e-3f,  3.5921280e-3f);
        c5 = pack2(-8.8632355e-3f, -8.8632355e-3f);
        c4 = pack2( 2.1869489e-2f,  2.1869489e-2f);
        c3 = pack2(-5.3968254e-2f, -5.3968254e-2f);
        c2 = pack2( 1.3333334e-1f,  1.3333334e-1f);
        c1 = pack2(-3.3333334e-1f, -3.3333334e-1f);
        c0 = pack2( 1.0f, 1.0f);
    }
    __device__ __forceinline__ u64t tanh2(float xa, float xb) const {
        if (__builtin_expect(fmaxf(fabsf(xa), fabsf(xb)) > 0.8f, 0))
            return pack2(tanhf(xa), tanhf(xb));
        u64t x = pack2(xa, xb);
        u64t t = mul2(x, x);
        u64t p = fma2(c6, t, c5);
        p = fma2(p, t, c4);
        p = fma2(p, t, c3);
        p = fma2(p, t, c2);
        p = fma2(p, t, c1);
        p = fma2(p, t, c0);
        return mul2(x, p);
    }
};

// ---------------------------------------------------------------------------
// Node GEMM: out_half = emb @ xi_w[half*128 : half*128+128, :] (+ xi_b if 0)
// ---------------------------------------------------------------------------
__global__ __launch_bounds__(256, 2)
void k_nodegemm(const float* __restrict__ emb, const float* __restrict__ xiw,
                const float* __restrict__ xib, int V)
{
    __shared__ float XsT[128 * PITCH];    // XsT[k][r] = emb[v0+r][k]
    const int tid  = threadIdx.x;
    const int v0   = blockIdx.x * 64;
    const int half = blockIdx.y;

    #pragma unroll 4
    for (int i = 0; i < 32; ++i) {
        int idx = tid + (i << 8);
        int r = idx >> 7, k = idx & 127;
        int v = v0 + r;
        XsT[k * PITCH + r] = (v < V) ? __ldg(&emb[(size_t)v * 128 + k]) : 0.f;
    }
    __syncthreads();

    const int col4 = (tid & 63) * 4;
    const int rb   = (tid >> 6) * 16;

    u64t acc[8][4];
    #pragma unroll
    for (int p = 0; p < 8; ++p)
        #pragma unroll
        for (int c = 0; c < 4; ++c) acc[p][c] = 0ull;

    const float* wbase = xiw + (size_t)(half * 128) * 256;
    #pragma unroll 4
    for (int k = 0; k < 128; ++k) {
        const float4 w = __ldg((const float4*)(wbase + ((size_t)k << 8) + col4));
        u64t wd[4];
        wd[0] = pack2(w.x, w.x); wd[1] = pack2(w.y, w.y);
        wd[2] = pack2(w.z, w.z); wd[3] = pack2(w.w, w.w);
        const ulonglong2* xp = (const ulonglong2*)(XsT + k * PITCH + rb);
        ulonglong2 x0 = xp[0], x1 = xp[1], x2 = xp[2], x3 = xp[3];
        u64t xv[8] = { x0.x, x0.y, x1.x, x1.y, x2.x, x2.y, x3.x, x3.y };
        #pragma unroll
        for (int p = 0; p < 8; ++p)
            #pragma unroll
            for (int c = 0; c < 4; ++c)
                fma2_acc(acc[p][c], xv[p], wd[c]);
    }

    float4 bias = make_float4(0.f, 0.f, 0.f, 0.f);
    if (half == 0) bias = __ldg((const float4*)(xib + col4));
    float* dst = half ? g_Q : g_P;

    #pragma unroll
    for (int p = 0; p < 8; ++p) {
        int ra = rb + 2 * p;
        float va[4], vb[4];
        unpack2(acc[p][0], va[0], vb[0]);
        unpack2(acc[p][1], va[1], vb[1]);
        unpack2(acc[p][2], va[2], vb[2]);
        unpack2(acc[p][3], va[3], vb[3]);
        if (v0 + ra < V) {
            float4 o = make_float4(va[0] + bias.x, va[1] + bias.y,
                                   va[2] + bias.z, va[3] + bias.w);
            *(float4*)(dst + (size_t)(v0 + ra) * 256 + col4) = o;
        }
        if (v0 + ra + 1 < V) {
            float4 o = make_float4(vb[0] + bias.x, vb[1] + bias.y,
                                   vb[2] + bias.z, vb[3] + bias.w);
            *(float4*)(dst + (size_t)(v0 + ra + 1) * 256 + col4) = o;
        }
    }
}

// ---------------------------------------------------------------------------
// R = tanh(emb @ rou_w + rou_b)   (16 threads per node)
// ---------------------------------------------------------------------------
__global__ __launch_bounds__(256)
void k_R(const float* __restrict__ emb, const float* __restrict__ rw,
         const float* __restrict__ rb, int V)
{
    __shared__ float rwT[16 * 132];
    const int tid = threadIdx.x;
    for (int idx = tid; idx < 2048; idx += 256) {
        int k = idx >> 4, j = idx & 15;
        rwT[j * 132 + k] = rw[idx];
    }
    __syncthreads();
    int v = blockIdx.x * 16 + (tid >> 4);
    int j = tid & 15;
    if (v >= V) return;
    const float* er = emb + (size_t)v * 128;
    const float* wr = rwT + j * 132;
    float acc = __ldg(&rb[j]);
    #pragma unroll
    for (int k = 0; k < 128; k += 4) {
        float4 xv = __ldg((const float4*)(er + k));
        float4 wv = *(const float4*)(wr + k);
        acc = fmaf(xv.x, wv.x, acc);
        acc = fmaf(xv.y, wv.y, acc);
        acc = fmaf(xv.z, wv.z, acc);
        acc = fmaf(xv.w, wv.w, acc);
    }
    g_R[v * 16 + j] = tanh_fast(acc);
}

// ---------------------------------------------------------------------------
// states utilities
// ---------------------------------------------------------------------------
__global__ void k_zero(int sel, int n) {
    float* p = sel ? g_s1 : g_s0;
    int i = blockIdx.x * blockDim.x + threadIdx.x;
    if (i < n) p[i] = 0.f;
}

// Step 1 (states=0 => H=R[src]): scatter-add R[src] to nbr.
__global__ void k_prop_first(const int* __restrict__ Xn, const int* __restrict__ Xe,
                             int sel_out, int E) {
    float* out = sel_out ? g_s1 : g_s0;
    int idx = blockIdx.x * blockDim.x + threadIdx.x;
    if (idx >= E * 16) return;
    int e = idx >> 4, i = idx & 15;
    atomicAdd(&out[__ldg(&Xe[e]) * 16 + i],
              __ldg(&g_R[__ldg(&Xn[e]) * 16 + i]));
}

// Fused step: A_e recomputed on the fly from P/Q (L2-resident).
//   H[s] = sc * sum_t tanh(P[src][s*16+t] + Q[nbr][s*16+t]) * h[t] + R[src][s]
// 16 lanes per edge (lane = s); packed f32x2 tanh + matvec.
__global__ __launch_bounds__(256)
void k_prop_fused(const int* __restrict__ Xn, const int* __restrict__ Xe,
                  const int* __restrict__ dg, int sel_in, int E)
{
    const float* in  = sel_in ? g_s1 : g_s0;
    float*       out = sel_in ? g_s0 : g_s1;
    int idx = blockIdx.x * 256 + threadIdx.x;
    int e = idx >> 4, s = idx & 15;
    if (e >= E) return;   // E*16 multiple of 256; warp-uniform

    TanhC tc; tc.init();

    const int src = __ldg(&Xn[e]);
    const int nbr = __ldg(&Xe[e]);
    const float sc = 0.05625f / (float)__ldg(&dg[e]);

    const float h = in[src * 16 + s];
    u64t hp[8];
    #pragma unroll
    for (int j = 0; j < 8; ++j) {
        float ha = __shfl_sync(0xffffffffu, h, 2 * j,     16);
        float hb = __shfl_sync(0xffffffffu, h, 2 * j + 1, 16);
        hp[j] = pack2(ha, hb);
    }

    const float4* Pr = (const float4*)(g_P + (size_t)src * 256 + s * 16);
    const float4* Qr = (const float4*)(g_Q + (size_t)nbr * 256 + s * 16);

    u64t acc2 = 0ull;
    #pragma unroll
    for (int q4 = 0; q4 < 4; ++q4) {
        float4 p = __ldg(Pr + q4);
        float4 q = __ldg(Qr + q4);
        fma2_acc(acc2, tc.tanh2(p.x + q.x, p.y + q.y), hp[2 * q4]);
        fma2_acc(acc2, tc.tanh2(p.z + q.z, p.w + q.w), hp[2 * q4 + 1]);
    }
    float ra, rb2;
    unpack2(acc2, ra, rb2);
    float res = fmaf(sc, ra + rb2, __ldg(&g_R[src * 16 + s]));
    atomicAdd(&out[nbr * 16 + s], res);
}

// ---------------------------------------------------------------------------
// Readout: logits = concat(emb, states) @ lin_w + lin_b, softmax.  Warp/node.
// ---------------------------------------------------------------------------
__global__ __launch_bounds__(256)
void k_final(const float* __restrict__ emb, const float* __restrict__ lw,
             const float* __restrict__ lb, float* __restrict__ out,
             int sel_states, int V)
{
    const float* st = sel_states ? g_s1 : g_s0;
    int v = (blockIdx.x * blockDim.x + threadIdx.x) >> 5;
    int lane = threadIdx.x & 31;
    if (v >= V) return;
    float p0 = 0.f, p1 = 0.f, p2 = 0.f;
    #pragma unroll
    for (int m = 0; m < 4; ++m) {
        int row = lane + 32 * m;
        float f = __ldg(&emb[(size_t)v * 128 + row]);
        p0 = fmaf(f, __ldg(&lw[row * 3 + 0]), p0);
        p1 = fmaf(f, __ldg(&lw[row * 3 + 1]), p1);
        p2 = fmaf(f, __ldg(&lw[row * 3 + 2]), p2);
    }
    if (lane < 16) {
        float sv = st[v * 16 + lane];
        int row = 128 + lane;
        p0 = fmaf(sv, __ldg(&lw[row * 3 + 0]), p0);
        p1 = fmaf(sv, __ldg(&lw[row * 3 + 1]), p1);
        p2 = fmaf(sv, __ldg(&lw[row * 3 + 2]), p2);
    }
    #pragma unroll
    for (int off = 16; off > 0; off >>= 1) {
        p0 += __shfl_xor_sync(0xffffffffu, p0, off);
        p1 += __shfl_xor_sync(0xffffffffu, p1, off);
        p2 += __shfl_xor_sync(0xffffffffu, p2, off);
    }
    if (lane == 0) {
        p0 += __ldg(&lb[0]); p1 += __ldg(&lb[1]); p2 += __ldg(&lb[2]);
        float mx = fmaxf(p0, fmaxf(p1, p2));
        float e0 = expf(p0 - mx), e1 = expf(p1 - mx), e2 = expf(p2 - mx);
        float inv = 1.f / (e0 + e1 + e2);
        out[(size_t)v * 3 + 0] = e0 * inv;
        out[(size_t)v * 3 + 1] = e1 * inv;
        out[(size_t)v * 3 + 2] = e2 * inv;
    }
}

// ---------------------------------------------------------------------------
extern "C" void kernel_launch(void* const* d_in, const int* in_sizes, int n_in,
                              void* d_out, int out_size)
{
    const int*   X_Node = (const int*)  d_in[0];
    const int*   X_Neis = (const int*)  d_in[1];
    const int*   dg     = (const int*)  d_in[2];
    const float* emb    = (const float*)d_in[3];
    const float* xi_w   = (const float*)d_in[4];
    const float* xi_b   = (const float*)d_in[5];
    const float* rou_w  = (const float*)d_in[6];
    const float* rou_b  = (const float*)d_in[7];
    const float* lin_w  = (const float*)d_in[8];
    const float* lin_b  = (const float*)d_in[9];
    float* out = (float*)d_out;
    const int E = in_sizes[0];
    const int V = in_sizes[3] / 128;

    // Node-level precompute: P = emb@W_top + xi_b, Q = emb@W_bot, R table.
    dim3 ggrid((V + 63) / 64, 2);
    k_nodegemm<<<ggrid, 256>>>(emb, xi_w, xi_b, V);
    k_R<<<(V + 15) / 16, 256>>>(emb, rou_w, rou_b, V);

    const int nS = V * 16;
    const int zb = (nS + 255) / 256;
    const int pb = (E * 16 + 255) / 256;

    // step 1 (states=0 => H=R[src]): scatter into s0
    k_zero<<<zb, 256>>>(0, nS);
    k_prop_first<<<pb, 256>>>(X_Node, X_Neis, 0, E);
    // step 2: s0 -> s1 (fused A recompute)
    k_zero<<<zb, 256>>>(1, nS);
    k_prop_fused<<<pb, 256>>>(X_Node, X_Neis, dg, 0, E);
    // step 3: s1 -> s0
    k_zero<<<zb, 256>>>(0, nS);
    k_prop_fused<<<pb, 256>>>(X_Node, X_Neis, dg, 1, E);

    k_final<<<(V + 7) / 8, 256>>>(emb, lin_w, lin_b, out, 0, V);
}

// round 8
// speedup vs baseline: 5.0338x; 1.3296x over previous
#include <cuda_runtime.h>
#include <cuda_fp16.h>
#include <math.h>
#include <string.h>
#include <stdint.h>

// Problem constants (fixed by the dataset)
#define MAX_E 500000
#define MAX_V 50000
#define PITCH 68   // padded shared pitch (floats): 16B aligned

// Scratch (allocation-free rule: __device__ globals)
static __device__ __half g_P[(size_t)MAX_V * 256];  // fp16: emb @ W_top + xi_b
static __device__ __half g_Q[(size_t)MAX_V * 256];  // fp16: emb @ W_bot
static __device__ float  g_R[MAX_V * 16];           // tanh(emb @ rou_w + rou_b)
static __device__ float  g_s0[MAX_V * 16];
static __device__ float  g_s1[MAX_V * 16];

// Bit-cast helpers (defined-behavior memcpy form; compiles to register moves)
__device__ __forceinline__ uint32_t h2_as_u32(__half2 h) {
    uint32_t u; memcpy(&u, &h, 4); return u;
}
__device__ __forceinline__ __half2 u32_as_h2(uint32_t u) {
    __half2 h; memcpy(&h, &u, 4); return h;
}

// ---------------------------------------------------------------------------
// Fast tanh (scalar): odd deg-13 poly for |x|<=0.8; tanhf fallback.
// ---------------------------------------------------------------------------
__device__ __forceinline__ float tanh_fast(float x) {
    float t = x * x;
    if (t > 0.64f) return tanhf(x);
    float p = 3.5921280e-3f;
    p = fmaf(p, t, -8.8632355e-3f);
    p = fmaf(p, t,  2.1869489e-2f);
    p = fmaf(p, t, -5.3968254e-2f);
    p = fmaf(p, t,  1.3333334e-1f);
    p = fmaf(p, t, -3.3333334e-1f);
    p = fmaf(p, t,  1.0f);
    return x * p;
}

// ---------------------------------------------------------------------------
// Packed f32x2 helpers (full-rate fp32 math on Blackwell)
// ---------------------------------------------------------------------------
typedef unsigned long long u64t;
__device__ __forceinline__ u64t pack2(float a, float b) {
    u64t r; asm("mov.b64 %0, {%1, %2};" : "=l"(r) : "f"(a), "f"(b)); return r;
}
__device__ __forceinline__ void unpack2(u64t v, float& a, float& b) {
    asm("mov.b64 {%0, %1}, %2;" : "=f"(a), "=f"(b) : "l"(v));
}
__device__ __forceinline__ void fma2_acc(u64t& d, u64t a, u64t b) {
    asm("fma.rn.f32x2 %0, %1, %2, %0;" : "+l"(d) : "l"(a), "l"(b));
}
__device__ __forceinline__ u64t fma2(u64t a, u64t b, u64t c) {
    u64t d; asm("fma.rn.f32x2 %0, %1, %2, %3;" : "=l"(d) : "l"(a), "l"(b), "l"(c)); return d;
}
__device__ __forceinline__ u64t mul2(u64t a, u64t b) {
    u64t d; asm("mul.rn.f32x2 %0, %1, %2;" : "=l"(d) : "l"(a), "l"(b)); return d;
}

// Packed tanh on a pair (as u64 f32x2); rare out-of-range -> tanhf fallback.
struct TanhC {
    u64t c6, c5, c4, c3, c2, c1, c0;
    __device__ __forceinline__ void init() {
        c6 = pack2( 3.5921280e-3f,  3.5921280e-3f);
        c5 = pack2(-8.8632355e-3f, -8.8632355e-3f);
        c4 = pack2( 2.1869489e-2f,  2.1869489e-2f);
        c3 = pack2(-5.3968254e-2f, -5.3968254e-2f);
        c2 = pack2( 1.3333334e-1f,  1.3333334e-1f);
        c1 = pack2(-3.3333334e-1f, -3.3333334e-1f);
        c0 = pack2( 1.0f, 1.0f);
    }
    __device__ __forceinline__ u64t tanh2(float xa, float xb) const {
        if (__builtin_expect(fmaxf(fabsf(xa), fabsf(xb)) > 0.8f, 0))
            return pack2(tanhf(xa), tanhf(xb));
        u64t x = pack2(xa, xb);
        u64t t = mul2(x, x);
        u64t p = fma2(c6, t, c5);
        p = fma2(p, t, c4);
        p = fma2(p, t, c3);
        p = fma2(p, t, c2);
        p = fma2(p, t, c1);
        p = fma2(p, t, c0);
        return mul2(x, p);
    }
};

// ---------------------------------------------------------------------------
// Node GEMM (both halves in one block, shared X tile reused):
//   P = emb @ xi_w[0:128,:] + xi_b   (fp16 out)
//   Q = emb @ xi_w[128:256,:]        (fp16 out)
// Tile: 64 nodes x 256 cols, K=128 per half.  Thread: 4 cols x 16 nodes.
// ---------------------------------------------------------------------------
static __global__ __launch_bounds__(256, 2)
void k_nodegemm(const float* __restrict__ emb, const float* __restrict__ xiw,
                const float* __restrict__ xib, int V)
{
    __shared__ float XsT[128 * PITCH];    // XsT[k][r] = emb[v0+r][k]
    const int tid = threadIdx.x;
    const int v0  = blockIdx.x * 64;

    #pragma unroll 4
    for (int i = 0; i < 32; ++i) {
        int idx = tid + (i << 8);
        int r = idx >> 7, k = idx & 127;
        int v = v0 + r;
        XsT[k * PITCH + r] = (v < V) ? __ldg(&emb[(size_t)v * 128 + k]) : 0.f;
    }
    __syncthreads();

    const int col4 = (tid & 63) * 4;
    const int rb   = (tid >> 6) * 16;

    #pragma unroll 1
    for (int half = 0; half < 2; ++half) {
        u64t acc[8][4];
        #pragma unroll
        for (int p = 0; p < 8; ++p)
            #pragma unroll
            for (int c = 0; c < 4; ++c) acc[p][c] = 0ull;

        const float* wbase = xiw + (size_t)(half * 128) * 256;
        #pragma unroll 4
        for (int k = 0; k < 128; ++k) {
            const float4 w = __ldg((const float4*)(wbase + ((size_t)k << 8) + col4));
            u64t wd[4];
            wd[0] = pack2(w.x, w.x); wd[1] = pack2(w.y, w.y);
            wd[2] = pack2(w.z, w.z); wd[3] = pack2(w.w, w.w);
            const ulonglong2* xp = (const ulonglong2*)(XsT + k * PITCH + rb);
            ulonglong2 x0 = xp[0], x1 = xp[1], x2 = xp[2], x3 = xp[3];
            u64t xv[8] = { x0.x, x0.y, x1.x, x1.y, x2.x, x2.y, x3.x, x3.y };
            #pragma unroll
            for (int p = 0; p < 8; ++p)
                #pragma unroll
                for (int c = 0; c < 4; ++c)
                    fma2_acc(acc[p][c], xv[p], wd[c]);
        }

        float4 bias = make_float4(0.f, 0.f, 0.f, 0.f);
        if (half == 0) bias = __ldg((const float4*)(xib + col4));
        __half* dst = half ? g_Q : g_P;

        #pragma unroll
        for (int p = 0; p < 8; ++p) {
            int ra = rb + 2 * p;
            float va[4], vb[4];
            unpack2(acc[p][0], va[0], vb[0]);
            unpack2(acc[p][1], va[1], vb[1]);
            unpack2(acc[p][2], va[2], vb[2]);
            unpack2(acc[p][3], va[3], vb[3]);
            if (v0 + ra < V) {
                __half2 h0 = __floats2half2_rn(va[0] + bias.x, va[1] + bias.y);
                __half2 h1 = __floats2half2_rn(va[2] + bias.z, va[3] + bias.w);
                *(uint2*)(dst + (size_t)(v0 + ra) * 256 + col4) =
                    make_uint2(h2_as_u32(h0), h2_as_u32(h1));
            }
            if (v0 + ra + 1 < V) {
                __half2 h0 = __floats2half2_rn(vb[0] + bias.x, vb[1] + bias.y);
                __half2 h1 = __floats2half2_rn(vb[2] + bias.z, vb[3] + bias.w);
                *(uint2*)(dst + (size_t)(v0 + ra + 1) * 256 + col4) =
                    make_uint2(h2_as_u32(h0), h2_as_u32(h1));
            }
        }
    }
}

// ---------------------------------------------------------------------------
// R = tanh(emb @ rou_w + rou_b)   (16 threads per node)
// ---------------------------------------------------------------------------
static __global__ __launch_bounds__(256)
void k_R(const float* __restrict__ emb, const float* __restrict__ rw,
         const float* __restrict__ rb, int V)
{
    __shared__ float rwT[16 * 132];
    const int tid = threadIdx.x;
    for (int idx = tid; idx < 2048; idx += 256) {
        int k = idx >> 4, j = idx & 15;
        rwT[j * 132 + k] = rw[idx];
    }
    __syncthreads();
    int v = blockIdx.x * 16 + (tid >> 4);
    int j = tid & 15;
    if (v >= V) return;
    const float* er = emb + (size_t)v * 128;
    const float* wr = rwT + j * 132;
    float acc = __ldg(&rb[j]);
    #pragma unroll
    for (int k = 0; k < 128; k += 4) {
        float4 xv = __ldg((const float4*)(er + k));
        float4 wv = *(const float4*)(wr + k);
        acc = fmaf(xv.x, wv.x, acc);
        acc = fmaf(xv.y, wv.y, acc);
        acc = fmaf(xv.z, wv.z, acc);
        acc = fmaf(xv.w, wv.w, acc);
    }
    g_R[v * 16 + j] = tanh_fast(acc);
}

// ---------------------------------------------------------------------------
// states utilities
// ---------------------------------------------------------------------------
static __global__ void k_zero(int sel, int n) {
    float* p = sel ? g_s1 : g_s0;
    int i = blockIdx.x * blockDim.x + threadIdx.x;
    if (i < n) p[i] = 0.f;
}

// Step 1 (states=0 => H=R[src]): scatter-add R[src] to nbr.
static __global__ void k_prop_first(const int* __restrict__ Xn,
                                    const int* __restrict__ Xe,
                                    int sel_out, int E) {
    float* out = sel_out ? g_s1 : g_s0;
    int idx = blockIdx.x * blockDim.x + threadIdx.x;
    if (idx >= E * 16) return;
    int e = idx >> 4, i = idx & 15;
    atomicAdd(&out[__ldg(&Xe[e]) * 16 + i],
              __ldg(&g_R[__ldg(&Xn[e]) * 16 + i]));
}

// Fused step: A_e recomputed on the fly from fp16 P/Q (L2-resident).
//   H[s] = sc * sum_t tanh(P[src][s*16+t] + Q[nbr][s*16+t]) * h[t] + R[src][s]
// 16 lanes per edge (lane = s); half2 pairs feed packed f32x2 tanh.
static __global__ __launch_bounds__(256)
void k_prop_fused(const int* __restrict__ Xn, const int* __restrict__ Xe,
                  const int* __restrict__ dg, int sel_in, int E)
{
    const float* in  = sel_in ? g_s1 : g_s0;
    float*       out = sel_in ? g_s0 : g_s1;
    int idx = blockIdx.x * 256 + threadIdx.x;
    int e = idx >> 4, s = idx & 15;
    if (e >= E) return;   // E*16 multiple of 256; warp-uniform

    TanhC tc; tc.init();

    const int src = __ldg(&Xn[e]);
    const int nbr = __ldg(&Xe[e]);
    const float sc = 0.05625f / (float)__ldg(&dg[e]);

    const float h = in[src * 16 + s];
    u64t hp[8];
    #pragma unroll
    for (int j = 0; j < 8; ++j) {
        float ha = __shfl_sync(0xffffffffu, h, 2 * j,     16);
        float hb = __shfl_sync(0xffffffffu, h, 2 * j + 1, 16);
        hp[j] = pack2(ha, hb);
    }

    // 16 halves of P row + 16 of Q row: 2 x uint4 each.
    const uint4* Pr = (const uint4*)(g_P + (size_t)src * 256 + s * 16);
    const uint4* Qr = (const uint4*)(g_Q + (size_t)nbr * 256 + s * 16);

    u64t acc2 = 0ull;
    #pragma unroll
    for (int c = 0; c < 2; ++c) {                 // two 8-element chunks
        uint4 pu = __ldg(Pr + c);
        uint4 qu = __ldg(Qr + c);
        const uint32_t pw[4] = { pu.x, pu.y, pu.z, pu.w };
        const uint32_t qw[4] = { qu.x, qu.y, qu.z, qu.w };
        #pragma unroll
        for (int j = 0; j < 4; ++j) {             // each uint = half2 = one pair
            float2 pf = __half22float2(u32_as_h2(pw[j]));
            float2 qf = __half22float2(u32_as_h2(qw[j]));
            fma2_acc(acc2, tc.tanh2(pf.x + qf.x, pf.y + qf.y), hp[4 * c + j]);
        }
    }
    float ra, rb2;
    unpack2(acc2, ra, rb2);
    float res = fmaf(sc, ra + rb2, __ldg(&g_R[src * 16 + s]));
    atomicAdd(&out[nbr * 16 + s], res);
}

// ---------------------------------------------------------------------------
// Readout: logits = concat(emb, states) @ lin_w + lin_b, softmax.  Warp/node.
// ---------------------------------------------------------------------------
static __global__ __launch_bounds__(256)
void k_final(const float* __restrict__ emb, const float* __restrict__ lw,
             const float* __restrict__ lb, float* __restrict__ out,
             int sel_states, int V)
{
    const float* st = sel_states ? g_s1 : g_s0;
    int v = (blockIdx.x * blockDim.x + threadIdx.x) >> 5;
    int lane = threadIdx.x & 31;
    if (v >= V) return;
    float p0 = 0.f, p1 = 0.f, p2 = 0.f;
    #pragma unroll
    for (int m = 0; m < 4; ++m) {
        int row = lane + 32 * m;
        float f = __ldg(&emb[(size_t)v * 128 + row]);
        p0 = fmaf(f, __ldg(&lw[row * 3 + 0]), p0);
        p1 = fmaf(f, __ldg(&lw[row * 3 + 1]), p1);
        p2 = fmaf(f, __ldg(&lw[row * 3 + 2]), p2);
    }
    if (lane < 16) {
        float sv = st[v * 16 + lane];
        int row = 128 + lane;
        p0 = fmaf(sv, __ldg(&lw[row * 3 + 0]), p0);
        p1 = fmaf(sv, __ldg(&lw[row * 3 + 1]), p1);
        p2 = fmaf(sv, __ldg(&lw[row * 3 + 2]), p2);
    }
    #pragma unroll
    for (int off = 16; off > 0; off >>= 1) {
        p0 += __shfl_xor_sync(0xffffffffu, p0, off);
        p1 += __shfl_xor_sync(0xffffffffu, p1, off);
        p2 += __shfl_xor_sync(0xffffffffu, p2, off);
    }
    if (lane == 0) {
        p0 += __ldg(&lb[0]); p1 += __ldg(&lb[1]); p2 += __ldg(&lb[2]);
        float mx = fmaxf(p0, fmaxf(p1, p2));
        float e0 = expf(p0 - mx), e1 = expf(p1 - mx), e2 = expf(p2 - mx);
        float inv = 1.f / (e0 + e1 + e2);
        out[(size_t)v * 3 + 0] = e0 * inv;
        out[(size_t)v * 3 + 1] = e1 * inv;
        out[(size_t)v * 3 + 2] = e2 * inv;
    }
}

// ---------------------------------------------------------------------------
extern "C" void kernel_launch(void* const* d_in, const int* in_sizes, int n_in,
                              void* d_out, int out_size)
{
    const int*   X_Node = (const int*)  d_in[0];
    const int*   X_Neis = (const int*)  d_in[1];
    const int*   dg     = (const int*)  d_in[2];
    const float* emb    = (const float*)d_in[3];
    const float* xi_w   = (const float*)d_in[4];
    const float* xi_b   = (const float*)d_in[5];
    const float* rou_w  = (const float*)d_in[6];
    const float* rou_b  = (const float*)d_in[7];
    const float* lin_w  = (const float*)d_in[8];
    const float* lin_b  = (const float*)d_in[9];
    float* out = (float*)d_out;
    const int E = in_sizes[0];
    const int V = in_sizes[3] / 128;

    // Node-level precompute: P/Q (fp16), R table.
    k_nodegemm<<<(V + 63) / 64, 256>>>(emb, xi_w, xi_b, V);
    k_R<<<(V + 15) / 16, 256>>>(emb, rou_w, rou_b, V);

    const int nS = V * 16;
    const int zb = (nS + 255) / 256;
    const int pb = (E * 16 + 255) / 256;

    // step 1 (states=0 => H=R[src]): scatter into s0
    k_zero<<<zb, 256>>>(0, nS);
    k_prop_first<<<pb, 256>>>(X_Node, X_Neis, 0, E);
    // step 2: s0 -> s1 (fused A recompute)
    k_zero<<<zb, 256>>>(1, nS);
    k_prop_fused<<<pb, 256>>>(X_Node, X_Neis, dg, 0, E);
    // step 3: s1 -> s0
    k_zero<<<zb, 256>>>(0, nS);
    k_prop_fused<<<pb, 256>>>(X_Node, X_Neis, dg, 1, E);

    k_final<<<(V + 7) / 8, 256>>>(emb, lin_w, lin_b, out, 0, V);
}

// round 9
// speedup vs baseline: 5.6884x; 1.1300x over previous
#include <cuda_runtime.h>
#include <cuda_fp16.h>
#include <math.h>
#include <string.h>
#include <stdint.h>

// Problem constants (fixed by the dataset)
#define MAX_E 500000
#define MAX_V 50000
#define PITCH 68   // padded shared pitch (floats): 16B aligned

// Scratch (allocation-free rule: __device__ globals)
static __device__ __half g_P[(size_t)MAX_V * 256];  // fp16: emb @ W_top + xi_b
static __device__ __half g_Q[(size_t)MAX_V * 256];  // fp16: emb @ W_bot
static __device__ float  g_R[MAX_V * 16];           // tanh(emb @ rou_w + rou_b)
static __device__ float  g_s0[MAX_V * 16];
static __device__ float  g_s1[MAX_V * 16];
static __device__ float  g_s2[MAX_V * 16];

// Bit-cast helpers (defined-behavior memcpy form; compiles to register moves)
__device__ __forceinline__ uint32_t h2_as_u32(__half2 h) {
    uint32_t u; memcpy(&u, &h, 4); return u;
}
__device__ __forceinline__ __half2 u32_as_h2(uint32_t u) {
    __half2 h; memcpy(&h, &u, 4); return h;
}

// ---------------------------------------------------------------------------
// Fast tanh (scalar): odd deg-13 poly for |x|<=0.8; tanhf fallback.
// ---------------------------------------------------------------------------
__device__ __forceinline__ float tanh_fast(float x) {
    float t = x * x;
    if (t > 0.64f) return tanhf(x);
    float p = 3.5921280e-3f;
    p = fmaf(p, t, -8.8632355e-3f);
    p = fmaf(p, t,  2.1869489e-2f);
    p = fmaf(p, t, -5.3968254e-2f);
    p = fmaf(p, t,  1.3333334e-1f);
    p = fmaf(p, t, -3.3333334e-1f);
    p = fmaf(p, t,  1.0f);
    return x * p;
}

// ---------------------------------------------------------------------------
// Packed f32x2 helpers (full-rate fp32 math on Blackwell)
// ---------------------------------------------------------------------------
typedef unsigned long long u64t;
__device__ __forceinline__ u64t pack2(float a, float b) {
    u64t r; asm("mov.b64 %0, {%1, %2};" : "=l"(r) : "f"(a), "f"(b)); return r;
}
__device__ __forceinline__ void unpack2(u64t v, float& a, float& b) {
    asm("mov.b64 {%0, %1}, %2;" : "=f"(a), "=f"(b) : "l"(v));
}
__device__ __forceinline__ void fma2_acc(u64t& d, u64t a, u64t b) {
    asm("fma.rn.f32x2 %0, %1, %2, %0;" : "+l"(d) : "l"(a), "l"(b));
}
__device__ __forceinline__ u64t fma2(u64t a, u64t b, u64t c) {
    u64t d; asm("fma.rn.f32x2 %0, %1, %2, %3;" : "=l"(d) : "l"(a), "l"(b), "l"(c)); return d;
}
__device__ __forceinline__ u64t mul2(u64t a, u64t b) {
    u64t d; asm("mul.rn.f32x2 %0, %1, %2;" : "=l"(d) : "l"(a), "l"(b)); return d;
}

// Packed tanh on a pair (as u64 f32x2); rare out-of-range -> tanhf fallback.
struct TanhC {
    u64t c6, c5, c4, c3, c2, c1, c0;
    __device__ __forceinline__ void init() {
        c6 = pack2( 3.5921280e-3f,  3.5921280e-3f);
        c5 = pack2(-8.8632355e-3f, -8.8632355e-3f);
        c4 = pack2( 2.1869489e-2f,  2.1869489e-2f);
        c3 = pack2(-5.3968254e-2f, -5.3968254e-2f);
        c2 = pack2( 1.3333334e-1f,  1.3333334e-1f);
        c1 = pack2(-3.3333334e-1f, -3.3333334e-1f);
        c0 = pack2( 1.0f, 1.0f);
    }
    __device__ __forceinline__ u64t tanh2(float xa, float xb) const {
        if (__builtin_expect(fmaxf(fabsf(xa), fabsf(xb)) > 0.8f, 0))
            return pack2(tanhf(xa), tanhf(xb));
        u64t x = pack2(xa, xb);
        u64t t = mul2(x, x);
        u64t p = fma2(c6, t, c5);
        p = fma2(p, t, c4);
        p = fma2(p, t, c3);
        p = fma2(p, t, c2);
        p = fma2(p, t, c1);
        p = fma2(p, t, c0);
        return mul2(x, p);
    }
};

// ---------------------------------------------------------------------------
// K1 mega-kernel, role by blockIdx.x:
//   [0, NG)      node GEMM: P = emb@W_top + xi_b, Q = emb@W_bot (fp16 out)
//   [NG, 2NG)    R = tanh(emb @ rou_w + rou_b), 64 nodes/block
//   [2NG, +NZ)   zero s0, s1, s2 (grid-stride float4)
// Light R/zero blocks backfill SMs as gemm blocks drain.
// ---------------------------------------------------------------------------
#define NZB 192

static __global__ __launch_bounds__(256, 2)
void k_pre(const float* __restrict__ emb, const float* __restrict__ xiw,
           const float* __restrict__ xib, const float* __restrict__ rw,
           const float* __restrict__ rbias, int V, int NG)
{
    __shared__ float XsT[128 * PITCH];    // gemm: XsT[k][r] = emb[v0+r][k]
    __shared__ float rwT[16 * 132];       // R: transposed rou_w
    const int tid = threadIdx.x;
    const int bid = blockIdx.x;

    if (bid < NG) {
        // ---------------- node GEMM role ----------------
        const int v0 = bid * 64;
        #pragma unroll 4
        for (int i = 0; i < 32; ++i) {
            int idx = tid + (i << 8);
            int r = idx >> 7, k = idx & 127;
            int v = v0 + r;
            XsT[k * PITCH + r] = (v < V) ? __ldg(&emb[(size_t)v * 128 + k]) : 0.f;
        }
        __syncthreads();

        const int col4 = (tid & 63) * 4;
        const int rb   = (tid >> 6) * 16;

        #pragma unroll 1
        for (int half = 0; half < 2; ++half) {
            u64t acc[8][4];
            #pragma unroll
            for (int p = 0; p < 8; ++p)
                #pragma unroll
                for (int c = 0; c < 4; ++c) acc[p][c] = 0ull;

            const float* wbase = xiw + (size_t)(half * 128) * 256;
            #pragma unroll 4
            for (int k = 0; k < 128; ++k) {
                const float4 w = __ldg((const float4*)(wbase + ((size_t)k << 8) + col4));
                u64t wd[4];
                wd[0] = pack2(w.x, w.x); wd[1] = pack2(w.y, w.y);
                wd[2] = pack2(w.z, w.z); wd[3] = pack2(w.w, w.w);
                const ulonglong2* xp = (const ulonglong2*)(XsT + k * PITCH + rb);
                ulonglong2 x0 = xp[0], x1 = xp[1], x2 = xp[2], x3 = xp[3];
                u64t xv[8] = { x0.x, x0.y, x1.x, x1.y, x2.x, x2.y, x3.x, x3.y };
                #pragma unroll
                for (int p = 0; p < 8; ++p)
                    #pragma unroll
                    for (int c = 0; c < 4; ++c)
                        fma2_acc(acc[p][c], xv[p], wd[c]);
            }

            float4 bias = make_float4(0.f, 0.f, 0.f, 0.f);
            if (half == 0) bias = __ldg((const float4*)(xib + col4));
            __half* dst = half ? g_Q : g_P;

            #pragma unroll
            for (int p = 0; p < 8; ++p) {
                int ra = rb + 2 * p;
                float va[4], vb[4];
                unpack2(acc[p][0], va[0], vb[0]);
                unpack2(acc[p][1], va[1], vb[1]);
                unpack2(acc[p][2], va[2], vb[2]);
                unpack2(acc[p][3], va[3], vb[3]);
                if (v0 + ra < V) {
                    __half2 h0 = __floats2half2_rn(va[0] + bias.x, va[1] + bias.y);
                    __half2 h1 = __floats2half2_rn(va[2] + bias.z, va[3] + bias.w);
                    *(uint2*)(dst + (size_t)(v0 + ra) * 256 + col4) =
                        make_uint2(h2_as_u32(h0), h2_as_u32(h1));
                }
                if (v0 + ra + 1 < V) {
                    __half2 h0 = __floats2half2_rn(vb[0] + bias.x, vb[1] + bias.y);
                    __half2 h1 = __floats2half2_rn(vb[2] + bias.z, vb[3] + bias.w);
                    *(uint2*)(dst + (size_t)(v0 + ra + 1) * 256 + col4) =
                        make_uint2(h2_as_u32(h0), h2_as_u32(h1));
                }
            }
        }
    } else if (bid < 2 * NG) {
        // ---------------- R role: 64 nodes per block ----------------
        for (int idx = tid; idx < 2048; idx += 256) {
            int k = idx >> 4, j = idx & 15;
            rwT[j * 132 + k] = rw[idx];
        }
        __syncthreads();
        const int base = (bid - NG) * 64;
        const int j = tid & 15;
        const float* wr = rwT + j * 132;
        #pragma unroll 1
        for (int pass = 0; pass < 4; ++pass) {
            int v = base + pass * 16 + (tid >> 4);
            if (v >= V) continue;
            const float* er = emb + (size_t)v * 128;
            float acc = __ldg(&rbias[j]);
            #pragma unroll
            for (int k = 0; k < 128; k += 4) {
                float4 xv = __ldg((const float4*)(er + k));
                float4 wv = *(const float4*)(wr + k);
                acc = fmaf(xv.x, wv.x, acc);
                acc = fmaf(xv.y, wv.y, acc);
                acc = fmaf(xv.z, wv.z, acc);
                acc = fmaf(xv.w, wv.w, acc);
            }
            g_R[v * 16 + j] = tanh_fast(acc);
        }
    } else {
        // ---------------- zero role: s0, s1, s2 ----------------
        const int n4 = (V * 16) / 4;           // float4 count per buffer
        const int stride = NZB * 256;
        float4 z = make_float4(0.f, 0.f, 0.f, 0.f);
        for (int i = (bid - 2 * NG) * 256 + tid; i < n4; i += stride) {
            ((float4*)g_s0)[i] = z;
            ((float4*)g_s1)[i] = z;
            ((float4*)g_s2)[i] = z;
        }
    }
}

// ---------------------------------------------------------------------------
// Step 1 (states=0 => H=R[src]): scatter-add R[src] into s0.
// ---------------------------------------------------------------------------
static __global__ void k_prop_first(const int* __restrict__ Xn,
                                    const int* __restrict__ Xe, int E) {
    int idx = blockIdx.x * blockDim.x + threadIdx.x;
    if (idx >= E * 16) return;
    int e = idx >> 4, i = idx & 15;
    atomicAdd(&g_s0[__ldg(&Xe[e]) * 16 + i],
              __ldg(&g_R[__ldg(&Xn[e]) * 16 + i]));
}

// ---------------------------------------------------------------------------
// Fused step: A_e recomputed on the fly from fp16 P/Q (L2-resident).
//   H[s] = sc * sum_t tanh(P[src][s*16+t] + Q[nbr][s*16+t]) * h[t] + R[src][s]
// sel=0: s0 -> s1; sel=1: s1 -> s2.
// ---------------------------------------------------------------------------
static __global__ __launch_bounds__(256)
void k_prop_fused(const int* __restrict__ Xn, const int* __restrict__ Xe,
                  const int* __restrict__ dg, int sel, int E)
{
    const float* in  = sel ? g_s1 : g_s0;
    float*       out = sel ? g_s2 : g_s1;
    int idx = blockIdx.x * 256 + threadIdx.x;
    int e = idx >> 4, s = idx & 15;
    if (e >= E) return;   // E*16 multiple of 256; warp-uniform

    const int src = __ldg(&Xn[e]);
    const int nbr = __ldg(&Xe[e]);

    // Issue all long-latency loads up front (MLP).
    const uint4* Pr = (const uint4*)(g_P + (size_t)src * 256 + s * 16);
    const uint4* Qr = (const uint4*)(g_Q + (size_t)nbr * 256 + s * 16);
    const uint4 pu0 = __ldg(Pr + 0), pu1 = __ldg(Pr + 1);
    const uint4 qu0 = __ldg(Qr + 0), qu1 = __ldg(Qr + 1);
    const float h   = __ldg(&in[src * 16 + s]);
    const float rsv = __ldg(&g_R[src * 16 + s]);
    const float sc  = __fdividef(0.05625f, (float)__ldg(&dg[e]));

    TanhC tc; tc.init();

    u64t hp[8];
    #pragma unroll
    for (int j = 0; j < 8; ++j) {
        float ha = __shfl_sync(0xffffffffu, h, 2 * j,     16);
        float hb = __shfl_sync(0xffffffffu, h, 2 * j + 1, 16);
        hp[j] = pack2(ha, hb);
    }

    const uint32_t pw[8] = { pu0.x, pu0.y, pu0.z, pu0.w, pu1.x, pu1.y, pu1.z, pu1.w };
    const uint32_t qw[8] = { qu0.x, qu0.y, qu0.z, qu0.w, qu1.x, qu1.y, qu1.z, qu1.w };

    u64t acc2 = 0ull;
    #pragma unroll
    for (int j = 0; j < 8; ++j) {                 // each uint = half2 = one pair
        float2 pf = __half22float2(u32_as_h2(pw[j]));
        float2 qf = __half22float2(u32_as_h2(qw[j]));
        fma2_acc(acc2, tc.tanh2(pf.x + qf.x, pf.y + qf.y), hp[j]);
    }
    float ra, rb2;
    unpack2(acc2, ra, rb2);
    float res = fmaf(sc, ra + rb2, rsv);
    atomicAdd(&out[nbr * 16 + s], res);
}

// ---------------------------------------------------------------------------
// Readout: logits = concat(emb, s2) @ lin_w + lin_b, softmax.  Warp/node.
// ---------------------------------------------------------------------------
static __global__ __launch_bounds__(256)
void k_final(const float* __restrict__ emb, const float* __restrict__ lw,
             const float* __restrict__ lb, float* __restrict__ out, int V)
{
    int v = (blockIdx.x * blockDim.x + threadIdx.x) >> 5;
    int lane = threadIdx.x & 31;
    if (v >= V) return;
    float p0 = 0.f, p1 = 0.f, p2 = 0.f;
    #pragma unroll
    for (int m = 0; m < 4; ++m) {
        int row = lane + 32 * m;
        float f = __ldg(&emb[(size_t)v * 128 + row]);
        p0 = fmaf(f, __ldg(&lw[row * 3 + 0]), p0);
        p1 = fmaf(f, __ldg(&lw[row * 3 + 1]), p1);
        p2 = fmaf(f, __ldg(&lw[row * 3 + 2]), p2);
    }
    if (lane < 16) {
        float sv = g_s2[v * 16 + lane];
        int row = 128 + lane;
        p0 = fmaf(sv, __ldg(&lw[row * 3 + 0]), p0);
        p1 = fmaf(sv, __ldg(&lw[row * 3 + 1]), p1);
        p2 = fmaf(sv, __ldg(&lw[row * 3 + 2]), p2);
    }
    #pragma unroll
    for (int off = 16; off > 0; off >>= 1) {
        p0 += __shfl_xor_sync(0xffffffffu, p0, off);
        p1 += __shfl_xor_sync(0xffffffffu, p1, off);
        p2 += __shfl_xor_sync(0xffffffffu, p2, off);
    }
    if (lane == 0) {
        p0 += __ldg(&lb[0]); p1 += __ldg(&lb[1]); p2 += __ldg(&lb[2]);
        float mx = fmaxf(p0, fmaxf(p1, p2));
        float e0 = expf(p0 - mx), e1 = expf(p1 - mx), e2 = expf(p2 - mx);
        float inv = 1.f / (e0 + e1 + e2);
        out[(size_t)v * 3 + 0] = e0 * inv;
        out[(size_t)v * 3 + 1] = e1 * inv;
        out[(size_t)v * 3 + 2] = e2 * inv;
    }
}

// ---------------------------------------------------------------------------
extern "C" void kernel_launch(void* const* d_in, const int* in_sizes, int n_in,
                              void* d_out, int out_size)
{
    const int*   X_Node = (const int*)  d_in[0];
    const int*   X_Neis = (const int*)  d_in[1];
    const int*   dg     = (const int*)  d_in[2];
    const float* emb    = (const float*)d_in[3];
    const float* xi_w   = (const float*)d_in[4];
    const float* xi_b   = (const float*)d_in[5];
    const float* rou_w  = (const float*)d_in[6];
    const float* rou_b  = (const float*)d_in[7];
    const float* lin_w  = (const float*)d_in[8];
    const float* lin_b  = (const float*)d_in[9];
    float* out = (float*)d_out;
    const int E = in_sizes[0];
    const int V = in_sizes[3] / 128;

    const int NG = (V + 63) / 64;
    const int pb = (E * 16 + 255) / 256;

    // K1: node GEMM (P/Q fp16) + R table + zero s0/s1/s2, one launch.
    k_pre<<<2 * NG + NZB, 256>>>(emb, xi_w, xi_b, rou_w, rou_b, V, NG);
    // step 1 (states=0 => H=R[src]): scatter into s0
    k_prop_first<<<pb, 256>>>(X_Node, X_Neis, E);
    // step 2: s0 -> s1 ; step 3: s1 -> s2  (fused A recompute)
    k_prop_fused<<<pb, 256>>>(X_Node, X_Neis, dg, 0, E);
    k_prop_fused<<<pb, 256>>>(X_Node, X_Neis, dg, 1, E);
    // readout from s2
    k_final<<<(V + 7) / 8, 256>>>(emb, lin_w, lin_b, out, V);
}

// round 10
// speedup vs baseline: 6.3718x; 1.1201x over previous
#include <cuda_runtime.h>
#include <cuda_fp16.h>
#include <math.h>
#include <string.h>
#include <stdint.h>

// Problem constants (fixed by the dataset)
#define MAX_E 500000
#define MAX_V 50000
#define PITCH 68   // padded shared pitch (floats): 16B aligned

// Scratch (allocation-free rule: __device__ globals)
static __device__ __half g_P[(size_t)MAX_V * 256];  // fp16: emb @ W_top + xi_b
static __device__ __half g_Q[(size_t)MAX_V * 256];  // fp16: emb @ W_bot
static __device__ float  g_R[MAX_V * 16];           // tanh(emb @ rou_w + rou_b)
static __device__ float  g_s0[MAX_V * 16];
static __device__ float  g_s1[MAX_V * 16];
static __device__ float  g_s2[MAX_V * 16];

// Bit-cast helpers (defined-behavior memcpy form; compiles to register moves)
__device__ __forceinline__ uint32_t h2_as_u32(__half2 h) {
    uint32_t u; memcpy(&u, &h, 4); return u;
}
__device__ __forceinline__ __half2 u32_as_h2(uint32_t u) {
    __half2 h; memcpy(&h, &u, 4); return h;
}

// ---------------------------------------------------------------------------
// Fast tanh (scalar): odd deg-13 poly for |x|<=0.8; tanhf fallback.
// (used in precompute paths only)
// ---------------------------------------------------------------------------
__device__ __forceinline__ float tanh_fast(float x) {
    float t = x * x;
    if (t > 0.64f) return tanhf(x);
    float p = 3.5921280e-3f;
    p = fmaf(p, t, -8.8632355e-3f);
    p = fmaf(p, t,  2.1869489e-2f);
    p = fmaf(p, t, -5.3968254e-2f);
    p = fmaf(p, t,  1.3333334e-1f);
    p = fmaf(p, t, -3.3333334e-1f);
    p = fmaf(p, t,  1.0f);
    return x * p;
}

// ---------------------------------------------------------------------------
// Packed f32x2 helpers (full-rate fp32 math on Blackwell)
// ---------------------------------------------------------------------------
typedef unsigned long long u64t;
__device__ __forceinline__ u64t pack2(float a, float b) {
    u64t r; asm("mov.b64 %0, {%1, %2};" : "=l"(r) : "f"(a), "f"(b)); return r;
}
__device__ __forceinline__ void unpack2(u64t v, float& a, float& b) {
    asm("mov.b64 {%0, %1}, %2;" : "=f"(a), "=f"(b) : "l"(v));
}
__device__ __forceinline__ void fma2_acc(u64t& d, u64t a, u64t b) {
    asm("fma.rn.f32x2 %0, %1, %2, %0;" : "+l"(d) : "l"(a), "l"(b));
}
__device__ __forceinline__ u64t fma2(u64t a, u64t b, u64t c) {
    u64t d; asm("fma.rn.f32x2 %0, %1, %2, %3;" : "=l"(d) : "l"(a), "l"(b), "l"(c)); return d;
}
__device__ __forceinline__ u64t mul2(u64t a, u64t b) {
    u64t d; asm("mul.rn.f32x2 %0, %1, %2;" : "=l"(d) : "l"(a), "l"(b)); return d;
}

// ---------------------------------------------------------------------------
// K1 mega-kernel, role by blockIdx.x:
//   [0, NG)      node GEMM: P = emb@W_top + xi_b, Q = emb@W_bot (fp16 out)
//   [NG, 2NG)    R = tanh(emb @ rou_w + rou_b), 64 nodes/block
//   [2NG, +NZ)   zero s0, s1, s2 (grid-stride float4)
// ---------------------------------------------------------------------------
#define NZB 192

static __global__ __launch_bounds__(256, 2)
void k_pre(const float* __restrict__ emb, const float* __restrict__ xiw,
           const float* __restrict__ xib, const float* __restrict__ rw,
           const float* __restrict__ rbias, int V, int NG)
{
    __shared__ float XsT[128 * PITCH];    // gemm: XsT[k][r] = emb[v0+r][k]
    __shared__ float rwT[16 * 132];       // R: transposed rou_w
    const int tid = threadIdx.x;
    const int bid = blockIdx.x;

    if (bid < NG) {
        // ---------------- node GEMM role ----------------
        const int v0 = bid * 64;
        #pragma unroll 4
        for (int i = 0; i < 32; ++i) {
            int idx = tid + (i << 8);
            int r = idx >> 7, k = idx & 127;
            int v = v0 + r;
            XsT[k * PITCH + r] = (v < V) ? __ldg(&emb[(size_t)v * 128 + k]) : 0.f;
        }
        __syncthreads();

        const int col4 = (tid & 63) * 4;
        const int rb   = (tid >> 6) * 16;

        #pragma unroll 1
        for (int half = 0; half < 2; ++half) {
            u64t acc[8][4];
            #pragma unroll
            for (int p = 0; p < 8; ++p)
                #pragma unroll
                for (int c = 0; c < 4; ++c) acc[p][c] = 0ull;

            const float* wbase = xiw + (size_t)(half * 128) * 256;
            #pragma unroll 4
            for (int k = 0; k < 128; ++k) {
                const float4 w = __ldg((const float4*)(wbase + ((size_t)k << 8) + col4));
                u64t wd[4];
                wd[0] = pack2(w.x, w.x); wd[1] = pack2(w.y, w.y);
                wd[2] = pack2(w.z, w.z); wd[3] = pack2(w.w, w.w);
                const ulonglong2* xp = (const ulonglong2*)(XsT + k * PITCH + rb);
                ulonglong2 x0 = xp[0], x1 = xp[1], x2 = xp[2], x3 = xp[3];
                u64t xv[8] = { x0.x, x0.y, x1.x, x1.y, x2.x, x2.y, x3.x, x3.y };
                #pragma unroll
                for (int p = 0; p < 8; ++p)
                    #pragma unroll
                    for (int c = 0; c < 4; ++c)
                        fma2_acc(acc[p][c], xv[p], wd[c]);
            }

            float4 bias = make_float4(0.f, 0.f, 0.f, 0.f);
            if (half == 0) bias = __ldg((const float4*)(xib + col4));
            __half* dst = half ? g_Q : g_P;

            #pragma unroll
            for (int p = 0; p < 8; ++p) {
                int ra = rb + 2 * p;
                float va[4], vb[4];
                unpack2(acc[p][0], va[0], vb[0]);
                unpack2(acc[p][1], va[1], vb[1]);
                unpack2(acc[p][2], va[2], vb[2]);
                unpack2(acc[p][3], va[3], vb[3]);
                if (v0 + ra < V) {
                    __half2 h0 = __floats2half2_rn(va[0] + bias.x, va[1] + bias.y);
                    __half2 h1 = __floats2half2_rn(va[2] + bias.z, va[3] + bias.w);
                    *(uint2*)(dst + (size_t)(v0 + ra) * 256 + col4) =
                        make_uint2(h2_as_u32(h0), h2_as_u32(h1));
                }
                if (v0 + ra + 1 < V) {
                    __half2 h0 = __floats2half2_rn(vb[0] + bias.x, vb[1] + bias.y);
                    __half2 h1 = __floats2half2_rn(vb[2] + bias.z, vb[3] + bias.w);
                    *(uint2*)(dst + (size_t)(v0 + ra + 1) * 256 + col4) =
                        make_uint2(h2_as_u32(h0), h2_as_u32(h1));
                }
            }
        }
    } else if (bid < 2 * NG) {
        // ---------------- R role: 64 nodes per block ----------------
        for (int idx = tid; idx < 2048; idx += 256) {
            int k = idx >> 4, j = idx & 15;
            rwT[j * 132 + k] = rw[idx];
        }
        __syncthreads();
        const int base = (bid - NG) * 64;
        const int j = tid & 15;
        const float* wr = rwT + j * 132;
        #pragma unroll 1
        for (int pass = 0; pass < 4; ++pass) {
            int v = base + pass * 16 + (tid >> 4);
            if (v >= V) continue;
            const float* er = emb + (size_t)v * 128;
            float acc = __ldg(&rbias[j]);
            #pragma unroll
            for (int k = 0; k < 128; k += 4) {
                float4 xv = __ldg((const float4*)(er + k));
                float4 wv = *(const float4*)(wr + k);
                acc = fmaf(xv.x, wv.x, acc);
                acc = fmaf(xv.y, wv.y, acc);
                acc = fmaf(xv.z, wv.z, acc);
                acc = fmaf(xv.w, wv.w, acc);
            }
            g_R[v * 16 + j] = tanh_fast(acc);
        }
    } else {
        // ---------------- zero role: s0, s1, s2 ----------------
        const int n4 = (V * 16) / 4;           // float4 count per buffer
        const int stride = NZB * 256;
        float4 z = make_float4(0.f, 0.f, 0.f, 0.f);
        for (int i = (bid - 2 * NG) * 256 + tid; i < n4; i += stride) {
            ((float4*)g_s0)[i] = z;
            ((float4*)g_s1)[i] = z;
            ((float4*)g_s2)[i] = z;
        }
    }
}

// ---------------------------------------------------------------------------
// Step 1 (states=0 => H=R[src]): scatter-add R[src] into s0.
// ---------------------------------------------------------------------------
static __global__ void k_prop_first(const int* __restrict__ Xn,
                                    const int* __restrict__ Xe, int E) {
    int idx = blockIdx.x * blockDim.x + threadIdx.x;
    if (idx >= E * 16) return;
    int e = idx >> 4, i = idx & 15;
    atomicAdd(&g_s0[__ldg(&Xe[e]) * 16 + i],
              __ldg(&g_R[__ldg(&Xn[e]) * 16 + i]));
}

// ---------------------------------------------------------------------------
// Fused step: A_e recomputed on the fly from fp16 P/Q (L2-resident).
//   H[s] = sc * sum_t tanh(P[src][s*16+t] + Q[nbr][s*16+t]) * h[t] + R[src][s]
// sel=0: s0 -> s1; sel=1: s1 -> s2.
// half2 adds + one range check per thread + deg-7 packed-f32x2 tanh poly.
// ---------------------------------------------------------------------------
static __global__ __launch_bounds__(256, 6)
void k_prop_fused(const int* __restrict__ Xn, const int* __restrict__ Xe,
                  const int* __restrict__ dg, int sel, int E)
{
    const float* in  = sel ? g_s1 : g_s0;
    float*       out = sel ? g_s2 : g_s1;
    int idx = blockIdx.x * 256 + threadIdx.x;
    int e = idx >> 4, s = idx & 15;
    if (e >= E) return;   // E*16 multiple of 256; warp-uniform

    const int src = __ldg(&Xn[e]);
    const int nbr = __ldg(&Xe[e]);

    // Issue all long-latency loads up front (MLP).
    const uint4* Pr = (const uint4*)(g_P + (size_t)src * 256 + s * 16);
    const uint4* Qr = (const uint4*)(g_Q + (size_t)nbr * 256 + s * 16);
    const uint4 pu0 = __ldg(Pr + 0), pu1 = __ldg(Pr + 1);
    const uint4 qu0 = __ldg(Qr + 0), qu1 = __ldg(Qr + 1);
    const float h   = __ldg(&in[src * 16 + s]);
    const float rsv = __ldg(&g_R[src * 16 + s]);
    const float sc  = __fdividef(0.05625f, (float)__ldg(&dg[e]));

    u64t hp[8];
    #pragma unroll
    for (int j = 0; j < 8; ++j) {
        float ha = __shfl_sync(0xffffffffu, h, 2 * j,     16);
        float hb = __shfl_sync(0xffffffffu, h, 2 * j + 1, 16);
        hp[j] = pack2(ha, hb);
    }

    // x = P + Q in half2 (extra fp16 rounding ~= existing fp16 noise).
    __half2 sv[8];
    sv[0] = __hadd2(u32_as_h2(pu0.x), u32_as_h2(qu0.x));
    sv[1] = __hadd2(u32_as_h2(pu0.y), u32_as_h2(qu0.y));
    sv[2] = __hadd2(u32_as_h2(pu0.z), u32_as_h2(qu0.z));
    sv[3] = __hadd2(u32_as_h2(pu0.w), u32_as_h2(qu0.w));
    sv[4] = __hadd2(u32_as_h2(pu1.x), u32_as_h2(qu1.x));
    sv[5] = __hadd2(u32_as_h2(pu1.y), u32_as_h2(qu1.y));
    sv[6] = __hadd2(u32_as_h2(pu1.z), u32_as_h2(qu1.z));
    sv[7] = __hadd2(u32_as_h2(pu1.w), u32_as_h2(qu1.w));

    // Single range check for all 16 values.
    __half2 m = __habs2(sv[0]);
    #pragma unroll
    for (int j = 1; j < 8; ++j) m = __hmax2(m, __habs2(sv[j]));
    const float mx = fmaxf(__low2float(m), __high2float(m));

    u64t acc2 = 0ull;
    if (__builtin_expect(mx <= 0.6f, 1)) {
        // deg-7 odd Taylor: x(1 - t/3 + 2t^2/15 - 17t^3/315), |x|<=0.6
        const u64t c3 = pack2(-5.3968254e-2f, -5.3968254e-2f);
        const u64t c2 = pack2( 1.3333334e-1f,  1.3333334e-1f);
        const u64t c1 = pack2(-3.3333334e-1f, -3.3333334e-1f);
        const u64t c0 = pack2( 1.0f, 1.0f);
        #pragma unroll
        for (int j = 0; j < 8; ++j) {
            float2 f = __half22float2(sv[j]);
            u64t x = pack2(f.x, f.y);
            u64t t = mul2(x, x);
            u64t p = fma2(c3, t, c2);
            p = fma2(p, t, c1);
            p = fma2(p, t, c0);
            fma2_acc(acc2, mul2(x, p), hp[j]);
        }
    } else {
        // Rare (~3e-4 of threads): exact fallback for the whole row segment.
        #pragma unroll
        for (int j = 0; j < 8; ++j) {
            float2 f = __half22float2(sv[j]);
            fma2_acc(acc2, pack2(tanhf(f.x), tanhf(f.y)), hp[j]);
        }
    }

    float ra, rb2;
    unpack2(acc2, ra, rb2);
    float res = fmaf(sc, ra + rb2, rsv);
    atomicAdd(&out[nbr * 16 + s], res);
}

// ---------------------------------------------------------------------------
// Readout: logits = concat(emb, s2) @ lin_w + lin_b, softmax.  Warp/node.
// ---------------------------------------------------------------------------
static __global__ __launch_bounds__(256)
void k_final(const float* __restrict__ emb, const float* __restrict__ lw,
             const float* __restrict__ lb, float* __restrict__ out, int V)
{
    int v = (blockIdx.x * blockDim.x + threadIdx.x) >> 5;
    int lane = threadIdx.x & 31;
    if (v >= V) return;
    float p0 = 0.f, p1 = 0.f, p2 = 0.f;
    #pragma unroll
    for (int m = 0; m < 4; ++m) {
        int row = lane + 32 * m;
        float f = __ldg(&emb[(size_t)v * 128 + row]);
        p0 = fmaf(f, __ldg(&lw[row * 3 + 0]), p0);
        p1 = fmaf(f, __ldg(&lw[row * 3 + 1]), p1);
        p2 = fmaf(f, __ldg(&lw[row * 3 + 2]), p2);
    }
    if (lane < 16) {
        float sv = g_s2[v * 16 + lane];
        int row = 128 + lane;
        p0 = fmaf(sv, __ldg(&lw[row * 3 + 0]), p0);
        p1 = fmaf(sv, __ldg(&lw[row * 3 + 1]), p1);
        p2 = fmaf(sv, __ldg(&lw[row * 3 + 2]), p2);
    }
    #pragma unroll
    for (int off = 16; off > 0; off >>= 1) {
        p0 += __shfl_xor_sync(0xffffffffu, p0, off);
        p1 += __shfl_xor_sync(0xffffffffu, p1, off);
        p2 += __shfl_xor_sync(0xffffffffu, p2, off);
    }
    if (lane == 0) {
        p0 += __ldg(&lb[0]); p1 += __ldg(&lb[1]); p2 += __ldg(&lb[2]);
        float mx = fmaxf(p0, fmaxf(p1, p2));
        float e0 = expf(p0 - mx), e1 = expf(p1 - mx), e2 = expf(p2 - mx);
        float inv = 1.f / (e0 + e1 + e2);
        out[(size_t)v * 3 + 0] = e0 * inv;
        out[(size_t)v * 3 + 1] = e1 * inv;
        out[(size_t)v * 3 + 2] = e2 * inv;
    }
}

// ---------------------------------------------------------------------------
extern "C" void kernel_launch(void* const* d_in, const int* in_sizes, int n_in,
                              void* d_out, int out_size)
{
    const int*   X_Node = (const int*)  d_in[0];
    const int*   X_Neis = (const int*)  d_in[1];
    const int*   dg     = (const int*)  d_in[2];
    const float* emb    = (const float*)d_in[3];
    const float* xi_w   = (const float*)d_in[4];
    const float* xi_b   = (const float*)d_in[5];
    const float* rou_w  = (const float*)d_in[6];
    const float* rou_b  = (const float*)d_in[7];
    const float* lin_w  = (const float*)d_in[8];
    const float* lin_b  = (const float*)d_in[9];
    float* out = (float*)d_out;
    const int E = in_sizes[0];
    const int V = in_sizes[3] / 128;

    const int NG = (V + 63) / 64;
    const int pb = (E * 16 + 255) / 256;

    // K1: node GEMM (P/Q fp16) + R table + zero s0/s1/s2, one launch.
    k_pre<<<2 * NG + NZB, 256>>>(emb, xi_w, xi_b, rou_w, rou_b, V, NG);
    // step 1 (states=0 => H=R[src]): scatter into s0
    k_prop_first<<<pb, 256>>>(X_Node, X_Neis, E);
    // step 2: s0 -> s1 ; step 3: s1 -> s2  (fused A recompute)
    k_prop_fused<<<pb, 256>>>(X_Node, X_Neis, dg, 0, E);
    k_prop_fused<<<pb, 256>>>(X_Node, X_Neis, dg, 1, E);
    // readout from s2
    k_final<<<(V + 7) / 8, 256>>>(emb, lin_w, lin_b, out, V);
}

// round 12
// speedup vs baseline: 8.3157x; 1.3051x over previous
#include <cuda_runtime.h>
#include <cuda_fp16.h>
#include <math.h>
#include <string.h>
#include <stdint.h>

// Problem constants (fixed by the dataset)
#define MAX_E 500000
#define MAX_V 50000

// Scratch (allocation-free rule: __device__ globals)
static __device__ __half g_P[(size_t)MAX_V * 256];  // fp16: emb @ W_top + xi_b
static __device__ __half g_Q[(size_t)MAX_V * 256];  // fp16: emb @ W_bot
static __device__ __half g_Eh[(size_t)MAX_V * 128]; // fp16 emb
static __device__ uint2  g_Wfrag[16384];            // xi_w in mma B-fragment order
static __device__ float  g_R[MAX_V * 16];           // tanh(emb @ rou_w + rou_b)
static __device__ float  g_s0[MAX_V * 16];
static __device__ float  g_s1[MAX_V * 16];
static __device__ float  g_s2[MAX_V * 16];

// Bit-cast helpers
__device__ __forceinline__ __half2 u32_as_h2(uint32_t u) {
    __half2 h; memcpy(&h, &u, 4); return h;
}

// ---------------------------------------------------------------------------
// Fast tanh (scalar): odd deg-13 poly for |x|<=0.8; tanhf fallback.
// ---------------------------------------------------------------------------
__device__ __forceinline__ float tanh_fast(float x) {
    float t = x * x;
    if (t > 0.64f) return tanhf(x);
    float p = 3.5921280e-3f;
    p = fmaf(p, t, -8.8632355e-3f);
    p = fmaf(p, t,  2.1869489e-2f);
    p = fmaf(p, t, -5.3968254e-2f);
    p = fmaf(p, t,  1.3333334e-1f);
    p = fmaf(p, t, -3.3333334e-1f);
    p = fmaf(p, t,  1.0f);
    return x * p;
}

// ---------------------------------------------------------------------------
// Packed f32x2 helpers
// ---------------------------------------------------------------------------
typedef unsigned long long u64t;
__device__ __forceinline__ u64t pack2(float a, float b) {
    u64t r; asm("mov.b64 %0, {%1, %2};" : "=l"(r) : "f"(a), "f"(b)); return r;
}
__device__ __forceinline__ void unpack2(u64t v, float& a, float& b) {
    asm("mov.b64 {%0, %1}, %2;" : "=f"(a), "=f"(b) : "l"(v));
}
__device__ __forceinline__ void fma2_acc(u64t& d, u64t a, u64t b) {
    asm("fma.rn.f32x2 %0, %1, %2, %0;" : "+l"(d) : "l"(a), "l"(b));
}
__device__ __forceinline__ u64t fma2(u64t a, u64t b, u64t c) {
    u64t d; asm("fma.rn.f32x2 %0, %1, %2, %3;" : "=l"(d) : "l"(a), "l"(b), "l"(c)); return d;
}
__device__ __forceinline__ u64t mul2(u64t a, u64t b) {
    u64t d; asm("mul.rn.f32x2 %0, %1, %2;" : "=l"(d) : "l"(a), "l"(b)); return d;
}

// m16n8k16 f16 HMMA with f32 accumulators
__device__ __forceinline__ void mma16816(float* d, uint32_t a0, uint32_t a1,
                                         uint32_t a2, uint32_t a3,
                                         uint32_t b0, uint32_t b1) {
    asm volatile(
        "mma.sync.aligned.m16n8k16.row.col.f32.f16.f16.f32 "
        "{%0,%1,%2,%3}, {%4,%5,%6,%7}, {%8,%9}, {%0,%1,%2,%3};"
        : "+f"(d[0]), "+f"(d[1]), "+f"(d[2]), "+f"(d[3])
        : "r"(a0), "r"(a1), "r"(a2), "r"(a3), "r"(b0), "r"(b1));
}

// ---------------------------------------------------------------------------
// k_prep: emb -> fp16 g_Eh, xi_w -> fragment-ordered g_Wfrag.
//   g_Wfrag layout: widx = ((half*8 + kstep)*32 + ntile)*32 + lane
//     .x = { W[k0][n], W[k0+1][n] }  .y = { W[k0+8][n], W[k0+9][n] }
//     where n = ntile*8 + lane/4, k0 = half*128 + kstep*16 + 2*(lane%4)
// ---------------------------------------------------------------------------
static __global__ void k_prep(const float* __restrict__ emb,
                              const float* __restrict__ xiw, int V)
{
    int idx = blockIdx.x * 256 + threadIdx.x;
    int ne2 = V * 64;                 // half2 count of emb
    if (idx < ne2) {
        float2 f = ((const float2*)emb)[idx];
        ((__half2*)g_Eh)[idx] = __floats2half2_rn(f.x, f.y);
    }
    int widx = idx - ne2;
    if (widx >= 0 && widx < 16384) {
        int t  = widx & 31;
        int nt = (widx >> 5) & 31;
        int ks = (widx >> 10) & 7;
        int hf = widx >> 13;
        int n  = nt * 8 + (t >> 2);
        int k0 = hf * 128 + ks * 16 + 2 * (t & 3);
        uint32_t h0 = __half_as_ushort(__float2half_rn(xiw[(k0    ) * 256 + n]));
        uint32_t h1 = __half_as_ushort(__float2half_rn(xiw[(k0 + 1) * 256 + n]));
        uint32_t h2 = __half_as_ushort(__float2half_rn(xiw[(k0 + 8) * 256 + n]));
        uint32_t h3 = __half_as_ushort(__float2half_rn(xiw[(k0 + 9) * 256 + n]));
        g_Wfrag[widx] = make_uint2(h0 | (h1 << 16), h2 | (h3 << 16));
    }
}

// ---------------------------------------------------------------------------
// K1 mega-kernel, role by blockIdx.x:
//   [0, NG)      node GEMM via mma.sync: P/Q fp16 (64 nodes x 256 cols/block)
//   [NG, 2NG)    R = tanh(emb @ rou_w + rou_b), 64 nodes/block
//   [2NG, +NZB)  zero s0, s1, s2
// ---------------------------------------------------------------------------
#define NZB 192
#define EPITCH 136   // smem emb tile pitch in halves (272B: 8B-aligned, conflict-free frags)

static __global__ __launch_bounds__(256, 2)
void k_pre(const float* __restrict__ emb, const float* __restrict__ xib,
           const float* __restrict__ rw, const float* __restrict__ rbias,
           int V, int NG)
{
    __shared__ __half XsT16[64 * EPITCH];
    __shared__ float rwT[16 * 132];
    const int tid = threadIdx.x;
    const int bid = blockIdx.x;

    if (bid < NG) {
        // ---------------- GEMM role (tensor core) ----------------
        const int v0 = bid * 64;
        // Load 64 emb rows (fp16) into padded smem tile; zero-pad tail rows.
        for (int i = tid; i < 2048; i += 256) {         // uint2 units: 64 x 32
            int r = i >> 5, c4 = i & 31;
            int v = v0 + r;
            uint2 val = make_uint2(0u, 0u);
            if (v < V) val = *(const uint2*)(g_Eh + (size_t)v * 128 + c4 * 4);
            *(uint2*)(XsT16 + r * EPITCH + c4 * 4) = val;
        }
        __syncthreads();

        const int wid = tid >> 5, t = tid & 31;
        const int ng = wid & 3;          // node group (16 nodes)
        const int ch = wid >> 2;         // column half (128 cols)
        const int r  = t >> 2, qt = t & 3;
        const __half* arow0 = XsT16 + (ng * 16 + r) * EPITCH;
        const __half* arow8 = arow0 + 8 * EPITCH;
        const int va = v0 + ng * 16 + r;
        const int vb = va + 8;

        #pragma unroll 1
        for (int half = 0; half < 2; ++half) {
            float d[16][4];
            #pragma unroll
            for (int j = 0; j < 16; ++j)
                { d[j][0] = d[j][1] = d[j][2] = d[j][3] = 0.f; }

            #pragma unroll
            for (int ks = 0; ks < 8; ++ks) {
                const int cofs = ks * 16 + 2 * qt;   // halves within row
                uint32_t a0 = *(const uint32_t*)(arow0 + cofs);
                uint32_t a1 = *(const uint32_t*)(arow8 + cofs);
                uint32_t a2 = *(const uint32_t*)(arow0 + cofs + 8);
                uint32_t a3 = *(const uint32_t*)(arow8 + cofs + 8);
                const uint2* base = g_Wfrag + (((half * 8 + ks) * 32 + ch * 16) * 32) + t;
                #pragma unroll
                for (int j = 0; j < 16; ++j) {
                    uint2 b = __ldg(base + j * 32);
                    mma16816(d[j], a0, a1, a2, a3, b.x, b.y);
                }
            }

            __half* dst = half ? g_Q : g_P;
            #pragma unroll
            for (int j = 0; j < 16; ++j) {
                const int n0 = (ch * 16 + j) * 8 + 2 * qt;
                float bx = 0.f, by = 0.f;
                if (half == 0) { bx = __ldg(&xib[n0]); by = __ldg(&xib[n0 + 1]); }
                if (va < V)
                    *(__half2*)(dst + (size_t)va * 256 + n0) =
                        __floats2half2_rn(d[j][0] + bx, d[j][1] + by);
                if (vb < V)
                    *(__half2*)(dst + (size_t)vb * 256 + n0) =
                        __floats2half2_rn(d[j][2] + bx, d[j][3] + by);
            }
        }
    } else if (bid < 2 * NG) {
        // ---------------- R role: 64 nodes per block ----------------
        for (int idx = tid; idx < 2048; idx += 256) {
            int k = idx >> 4, j = idx & 15;
            rwT[j * 132 + k] = rw[idx];
        }
        __syncthreads();
        const int base = (bid - NG) * 64;
        const int j = tid & 15;
        const float* wr = rwT + j * 132;
        #pragma unroll 1
        for (int pass = 0; pass < 4; ++pass) {
            int v = base + pass * 16 + (tid >> 4);
            if (v >= V) continue;
            const float* er = emb + (size_t)v * 128;
            float acc = __ldg(&rbias[j]);
            #pragma unroll
            for (int k = 0; k < 128; k += 4) {
                float4 xv = __ldg((const float4*)(er + k));
                float4 wv = *(const float4*)(wr + k);
                acc = fmaf(xv.x, wv.x, acc);
                acc = fmaf(xv.y, wv.y, acc);
                acc = fmaf(xv.z, wv.z, acc);
                acc = fmaf(xv.w, wv.w, acc);
            }
            g_R[v * 16 + j] = tanh_fast(acc);
        }
    } else {
        // ---------------- zero role: s0, s1, s2 ----------------
        const int n4 = (V * 16) / 4;
        const int stride = NZB * 256;
        float4 z = make_float4(0.f, 0.f, 0.f, 0.f);
        for (int i = (bid - 2 * NG) * 256 + tid; i < n4; i += stride) {
            ((float4*)g_s0)[i] = z;
            ((float4*)g_s1)[i] = z;
            ((float4*)g_s2)[i] = z;
        }
    }
}

// ---------------------------------------------------------------------------
// Step 1 (states=0 => H=R[src]): scatter-add R[src] into s0.
// ---------------------------------------------------------------------------
static __global__ void k_prop_first(const int* __restrict__ Xn,
                                    const int* __restrict__ Xe, int E) {
    int idx = blockIdx.x * blockDim.x + threadIdx.x;
    if (idx >= E * 16) return;
    int e = idx >> 4, i = idx & 15;
    atomicAdd(&g_s0[__ldg(&Xe[e]) * 16 + i],
              __ldg(&g_R[__ldg(&Xn[e]) * 16 + i]));
}

// ---------------------------------------------------------------------------
// Fused prop step (unchanged from round 10).
// ---------------------------------------------------------------------------
static __global__ __launch_bounds__(256, 6)
void k_prop_fused(const int* __restrict__ Xn, const int* __restrict__ Xe,
                  const int* __restrict__ dg, int sel, int E)
{
    const float* in  = sel ? g_s1 : g_s0;
    float*       out = sel ? g_s2 : g_s1;
    int idx = blockIdx.x * 256 + threadIdx.x;
    int e = idx >> 4, s = idx & 15;
    if (e >= E) return;

    const int src = __ldg(&Xn[e]);
    const int nbr = __ldg(&Xe[e]);

    const uint4* Pr = (const uint4*)(g_P + (size_t)src * 256 + s * 16);
    const uint4* Qr = (const uint4*)(g_Q + (size_t)nbr * 256 + s * 16);
    const uint4 pu0 = __ldg(Pr + 0), pu1 = __ldg(Pr + 1);
    const uint4 qu0 = __ldg(Qr + 0), qu1 = __ldg(Qr + 1);
    const float h   = __ldg(&in[src * 16 + s]);
    const float rsv = __ldg(&g_R[src * 16 + s]);
    const float sc  = __fdividef(0.05625f, (float)__ldg(&dg[e]));

    u64t hp[8];
    #pragma unroll
    for (int j = 0; j < 8; ++j) {
        float ha = __shfl_sync(0xffffffffu, h, 2 * j,     16);
        float hb = __shfl_sync(0xffffffffu, h, 2 * j + 1, 16);
        hp[j] = pack2(ha, hb);
    }

    __half2 sv[8];
    sv[0] = __hadd2(u32_as_h2(pu0.x), u32_as_h2(qu0.x));
    sv[1] = __hadd2(u32_as_h2(pu0.y), u32_as_h2(qu0.y));
    sv[2] = __hadd2(u32_as_h2(pu0.z), u32_as_h2(qu0.z));
    sv[3] = __hadd2(u32_as_h2(pu0.w), u32_as_h2(qu0.w));
    sv[4] = __hadd2(u32_as_h2(pu1.x), u32_as_h2(qu1.x));
    sv[5] = __hadd2(u32_as_h2(pu1.y), u32_as_h2(qu1.y));
    sv[6] = __hadd2(u32_as_h2(pu1.z), u32_as_h2(qu1.z));
    sv[7] = __hadd2(u32_as_h2(pu1.w), u32_as_h2(qu1.w));

    __half2 m = __habs2(sv[0]);
    #pragma unroll
    for (int j = 1; j < 8; ++j) m = __hmax2(m, __habs2(sv[j]));
    const float mx = fmaxf(__low2float(m), __high2float(m));

    u64t acc2 = 0ull;
    if (__builtin_expect(mx <= 0.6f, 1)) {
        const u64t c3 = pack2(-5.3968254e-2f, -5.3968254e-2f);
        const u64t c2 = pack2( 1.3333334e-1f,  1.3333334e-1f);
        const u64t c1 = pack2(-3.3333334e-1f, -3.3333334e-1f);
        const u64t c0 = pack2( 1.0f, 1.0f);
        #pragma unroll
        for (int j = 0; j < 8; ++j) {
            float2 f = __half22float2(sv[j]);
            u64t x = pack2(f.x, f.y);
            u64t t = mul2(x, x);
            u64t p = fma2(c3, t, c2);
            p = fma2(p, t, c1);
            p = fma2(p, t, c0);
            fma2_acc(acc2, mul2(x, p), hp[j]);
        }
    } else {
        #pragma unroll
        for (int j = 0; j < 8; ++j) {
            float2 f = __half22float2(sv[j]);
            fma2_acc(acc2, pack2(tanhf(f.x), tanhf(f.y)), hp[j]);
        }
    }

    float ra, rb2;
    unpack2(acc2, ra, rb2);
    float res = fmaf(sc, ra + rb2, rsv);
    atomicAdd(&out[nbr * 16 + s], res);
}

// ---------------------------------------------------------------------------
// Readout: logits = concat(emb, s2) @ lin_w + lin_b, softmax.  Warp/node.
// ---------------------------------------------------------------------------
static __global__ __launch_bounds__(256)
void k_final(const float* __restrict__ emb, const float* __restrict__ lw,
             const float* __restrict__ lb, float* __restrict__ out, int V)
{
    int v = (blockIdx.x * blockDim.x + threadIdx.x) >> 5;
    int lane = threadIdx.x & 31;
    if (v >= V) return;
    float p0 = 0.f, p1 = 0.f, p2 = 0.f;
    #pragma unroll
    for (int m = 0; m < 4; ++m) {
        int row = lane + 32 * m;
        float f = __ldg(&emb[(size_t)v * 128 + row]);
        p0 = fmaf(f, __ldg(&lw[row * 3 + 0]), p0);
        p1 = fmaf(f, __ldg(&lw[row * 3 + 1]), p1);
        p2 = fmaf(f, __ldg(&lw[row * 3 + 2]), p2);
    }
    if (lane < 16) {
        float sv = g_s2[v * 16 + lane];
        int row = 128 + lane;
        p0 = fmaf(sv, __ldg(&lw[row * 3 + 0]), p0);
        p1 = fmaf(sv, __ldg(&lw[row * 3 + 1]), p1);
        p2 = fmaf(sv, __ldg(&lw[row * 3 + 2]), p2);
    }
    #pragma unroll
    for (int off = 16; off > 0; off >>= 1) {
        p0 += __shfl_xor_sync(0xffffffffu, p0, off);
        p1 += __shfl_xor_sync(0xffffffffu, p1, off);
        p2 += __shfl_xor_sync(0xffffffffu, p2, off);
    }
    if (lane == 0) {
        p0 += __ldg(&lb[0]); p1 += __ldg(&lb[1]); p2 += __ldg(&lb[2]);
        float mx = fmaxf(p0, fmaxf(p1, p2));
        float e0 = expf(p0 - mx), e1 = expf(p1 - mx), e2 = expf(p2 - mx);
        float inv = 1.f / (e0 + e1 + e2);
        out[(size_t)v * 3 + 0] = e0 * inv;
        out[(size_t)v * 3 + 1] = e1 * inv;
        out[(size_t)v * 3 + 2] = e2 * inv;
    }
}

// ---------------------------------------------------------------------------
extern "C" void kernel_launch(void* const* d_in, const int* in_sizes, int n_in,
                              void* d_out, int out_size)
{
    const int*   X_Node = (const int*)  d_in[0];
    const int*   X_Neis = (const int*)  d_in[1];
    const int*   dg     = (const int*)  d_in[2];
    const float* emb    = (const float*)d_in[3];
    const float* xi_w   = (const float*)d_in[4];
    const float* xi_b   = (const float*)d_in[5];
    const float* rou_w  = (const float*)d_in[6];
    const float* rou_b  = (const float*)d_in[7];
    const float* lin_w  = (const float*)d_in[8];
    const float* lin_b  = (const float*)d_in[9];
    float* out = (float*)d_out;
    const int E = in_sizes[0];
    const int V = in_sizes[3] / 128;

    const int NG = (V + 63) / 64;
    const int pb = (E * 16 + 255) / 256;
    const int np = (V * 64 + 16384 + 255) / 256;

    // Prep: fp16 emb + fragment-ordered fp16 xi_w.
    k_prep<<<np, 256>>>(emb, xi_w, V);
    // K1: tensor-core node GEMM (P/Q fp16) + R table + zero s0/s1/s2.
    k_pre<<<2 * NG + NZB, 256>>>(emb, xi_b, rou_w, rou_b, V, NG);
    // step 1 (states=0 => H=R[src]): scatter into s0
    k_prop_first<<<pb, 256>>>(X_Node, X_Neis, E);
    // step 2: s0 -> s1 ; step 3: s1 -> s2  (fused A recompute)
    k_prop_fused<<<pb, 256>>>(X_Node, X_Neis, dg, 0, E);
    k_prop_fused<<<pb, 256>>>(X_Node, X_Neis, dg, 1, E);
    // readout from s2
    k_final<<<(V + 7) / 8, 256>>>(emb, lin_w, lin_b, out, V);
}

// round 15
// speedup vs baseline: 9.0414x; 1.0873x over previous
#include <cuda_runtime.h>
#include <cuda_fp16.h>
#include <math.h>
#include <string.h>
#include <stdint.h>

// Problem constants (fixed by the dataset)
#define MAX_E 500000
#define MAX_V 50000

// Scratch (allocation-free rule: __device__ globals)
static __device__ __align__(16) unsigned char g_P8[(size_t)MAX_V * 256]; // e4m3: emb@W_top + xi_b
static __device__ __align__(16) unsigned char g_Q8[(size_t)MAX_V * 256]; // e4m3: emb@W_bot
static __device__ __half g_Eh[(size_t)MAX_V * 128]; // fp16 emb
static __device__ uint2  g_Wfrag[16384];            // xi_w in mma B-fragment order
static __device__ float  g_R[MAX_V * 16];           // tanh(emb @ rou_w + rou_b)
static __device__ float  g_s0[MAX_V * 16];
static __device__ float  g_s1[MAX_V * 16];
static __device__ float  g_s2[MAX_V * 16];

// Bit-cast helpers
__device__ __forceinline__ __half2 u32_as_h2(uint32_t u) {
    __half2 h; memcpy(&h, &u, 4); return h;
}
// 2 x e4m3 (packed u16, low byte = first value) -> half2 (low half = first value)
__device__ __forceinline__ __half2 fp8x2_to_h2(unsigned short u) {
    uint32_t r;
    asm("cvt.rn.f16x2.e4m3x2 %0, %1;" : "=r"(r) : "h"(u));
    return u32_as_h2(r);
}
// pack (lo, hi) floats -> e4m3x2 u16 (first PTX src -> upper byte)
__device__ __forceinline__ unsigned short f2_to_fp8x2(float lo, float hi) {
    unsigned short r;
    asm("cvt.rn.satfinite.e4m3x2.f32 %0, %1, %2;" : "=h"(r) : "f"(hi), "f"(lo));
    return r;
}

// ---------------------------------------------------------------------------
// Fast tanh (scalar): odd deg-13 poly for |x|<=0.8; tanhf fallback.
// ---------------------------------------------------------------------------
__device__ __forceinline__ float tanh_fast(float x) {
    float t = x * x;
    if (t > 0.64f) return tanhf(x);
    float p = 3.5921280e-3f;
    p = fmaf(p, t, -8.8632355e-3f);
    p = fmaf(p, t,  2.1869489e-2f);
    p = fmaf(p, t, -5.3968254e-2f);
    p = fmaf(p, t,  1.3333334e-1f);
    p = fmaf(p, t, -3.3333334e-1f);
    p = fmaf(p, t,  1.0f);
    return x * p;
}

// ---------------------------------------------------------------------------
// Packed f32x2 helpers
// ---------------------------------------------------------------------------
typedef unsigned long long u64t;
__device__ __forceinline__ u64t pack2(float a, float b) {
    u64t r; asm("mov.b64 %0, {%1, %2};" : "=l"(r) : "f"(a), "f"(b)); return r;
}
__device__ __forceinline__ void unpack2(u64t v, float& a, float& b) {
    asm("mov.b64 {%0, %1}, %2;" : "=f"(a), "=f"(b) : "l"(v));
}
__device__ __forceinline__ void fma2_acc(u64t& d, u64t a, u64t b) {
    asm("fma.rn.f32x2 %0, %1, %2, %0;" : "+l"(d) : "l"(a), "l"(b));
}
__device__ __forceinline__ u64t fma2(u64t a, u64t b, u64t c) {
    u64t d; asm("fma.rn.f32x2 %0, %1, %2, %3;" : "=l"(d) : "l"(a), "l"(b), "l"(c)); return d;
}
__device__ __forceinline__ u64t mul2(u64t a, u64t b) {
    u64t d; asm("mul.rn.f32x2 %0, %1, %2;" : "=l"(d) : "l"(a), "l"(b)); return d;
}

// m16n8k16 f16 HMMA with f32 accumulators
__device__ __forceinline__ void mma16816(float* d, uint32_t a0, uint32_t a1,
                                         uint32_t a2, uint32_t a3,
                                         uint32_t b0, uint32_t b1) {
    asm volatile(
        "mma.sync.aligned.m16n8k16.row.col.f32.f16.f16.f32 "
        "{%0,%1,%2,%3}, {%4,%5,%6,%7}, {%8,%9}, {%0,%1,%2,%3};"
        : "+f"(d[0]), "+f"(d[1]), "+f"(d[2]), "+f"(d[3])
        : "r"(a0), "r"(a1), "r"(a2), "r"(a3), "r"(b0), "r"(b1));
}

// ---------------------------------------------------------------------------
// k_prep: emb -> fp16 g_Eh, xi_w -> fragment-ordered g_Wfrag.
//   g_Wfrag layout: widx = ((half*8 + kstep)*32 + ntile)*32 + lane
//     .x = { W[k0][n], W[k0+1][n] }  .y = { W[k0+8][n], W[k0+9][n] }
//     where n = ntile*8 + lane/4, k0 = half*128 + kstep*16 + 2*(lane%4)
// ---------------------------------------------------------------------------
static __global__ void k_prep(const float* __restrict__ emb,
                              const float* __restrict__ xiw, int V)
{
    int idx = blockIdx.x * 256 + threadIdx.x;
    int ne2 = V * 64;                 // half2 count of emb
    if (idx < ne2) {
        float2 f = ((const float2*)emb)[idx];
        ((__half2*)g_Eh)[idx] = __floats2half2_rn(f.x, f.y);
    }
    int widx = idx - ne2;
    if (widx >= 0 && widx < 16384) {
        int t  = widx & 31;
        int nt = (widx >> 5) & 31;
        int ks = (widx >> 10) & 7;
        int hf = widx >> 13;
        int n  = nt * 8 + (t >> 2);
        int k0 = hf * 128 + ks * 16 + 2 * (t & 3);
        uint32_t h0 = __half_as_ushort(__float2half_rn(xiw[(k0    ) * 256 + n]));
        uint32_t h1 = __half_as_ushort(__float2half_rn(xiw[(k0 + 1) * 256 + n]));
        uint32_t h2 = __half_as_ushort(__float2half_rn(xiw[(k0 + 8) * 256 + n]));
        uint32_t h3 = __half_as_ushort(__float2half_rn(xiw[(k0 + 9) * 256 + n]));
        g_Wfrag[widx] = make_uint2(h0 | (h1 << 16), h2 | (h3 << 16));
    }
}

// ---------------------------------------------------------------------------
// K1 mega-kernel, role by blockIdx.x:
//   [0, NG)      node GEMM via mma.sync: P/Q fp8 out (64 nodes x 256 cols/blk)
//   [NG, 2NG)    R = tanh(emb @ rou_w + rou_b), 64 nodes/block
//   [2NG, +NZB)  zero s0, s1, s2
// ---------------------------------------------------------------------------
#define NZB 192
#define EPITCH 136

static __global__ __launch_bounds__(256, 2)
void k_pre(const float* __restrict__ emb, const float* __restrict__ xib,
           const float* __restrict__ rw, const float* __restrict__ rbias,
           int V, int NG)
{
    __shared__ __half XsT16[64 * EPITCH];
    __shared__ float rwT[16 * 132];
    const int tid = threadIdx.x;
    const int bid = blockIdx.x;

    if (bid < NG) {
        // ---------------- GEMM role (tensor core) ----------------
        const int v0 = bid * 64;
        for (int i = tid; i < 2048; i += 256) {
            int r = i >> 5, c4 = i & 31;
            int v = v0 + r;
            uint2 val = make_uint2(0u, 0u);
            if (v < V) val = *(const uint2*)(g_Eh + (size_t)v * 128 + c4 * 4);
            *(uint2*)(XsT16 + r * EPITCH + c4 * 4) = val;
        }
        __syncthreads();

        const int wid = tid >> 5, t = tid & 31;
        const int ng = wid & 3;
        const int ch = wid >> 2;
        const int r  = t >> 2, qt = t & 3;
        const __half* arow0 = XsT16 + (ng * 16 + r) * EPITCH;
        const __half* arow8 = arow0 + 8 * EPITCH;
        const int va = v0 + ng * 16 + r;
        const int vb = va + 8;

        #pragma unroll 1
        for (int half = 0; half < 2; ++half) {
            float d[16][4];
            #pragma unroll
            for (int j = 0; j < 16; ++j)
                { d[j][0] = d[j][1] = d[j][2] = d[j][3] = 0.f; }

            #pragma unroll
            for (int ks = 0; ks < 8; ++ks) {
                const int cofs = ks * 16 + 2 * qt;
                uint32_t a0 = *(const uint32_t*)(arow0 + cofs);
                uint32_t a1 = *(const uint32_t*)(arow8 + cofs);
                uint32_t a2 = *(const uint32_t*)(arow0 + cofs + 8);
                uint32_t a3 = *(const uint32_t*)(arow8 + cofs + 8);
                const uint2* base = g_Wfrag + (((half * 8 + ks) * 32 + ch * 16) * 32) + t;
                #pragma unroll
                for (int j = 0; j < 16; ++j) {
                    uint2 b = __ldg(base + j * 32);
                    mma16816(d[j], a0, a1, a2, a3, b.x, b.y);
                }
            }

            unsigned char* dst = half ? g_Q8 : g_P8;
            #pragma unroll
            for (int j = 0; j < 16; ++j) {
                const int n0 = (ch * 16 + j) * 8 + 2 * qt;
                float bx = 0.f, by = 0.f;
                if (half == 0) { bx = __ldg(&xib[n0]); by = __ldg(&xib[n0 + 1]); }
                if (va < V)
                    *(unsigned short*)(dst + (size_t)va * 256 + n0) =
                        f2_to_fp8x2(d[j][0] + bx, d[j][1] + by);
                if (vb < V)
                    *(unsigned short*)(dst + (size_t)vb * 256 + n0) =
                        f2_to_fp8x2(d[j][2] + bx, d[j][3] + by);
            }
        }
    } else if (bid < 2 * NG) {
        // ---------------- R role: 64 nodes per block ----------------
        for (int idx = tid; idx < 2048; idx += 256) {
            int k = idx >> 4, j = idx & 15;
            rwT[j * 132 + k] = rw[idx];
        }
        __syncthreads();
        const int base = (bid - NG) * 64;
        const int j = tid & 15;
        const float* wr = rwT + j * 132;
        #pragma unroll 1
        for (int pass = 0; pass < 4; ++pass) {
            int v = base + pass * 16 + (tid >> 4);
            if (v >= V) continue;
            const float* er = emb + (size_t)v * 128;
            float acc = __ldg(&rbias[j]);
            #pragma unroll
            for (int k = 0; k < 128; k += 4) {
                float4 xv = __ldg((const float4*)(er + k));
                float4 wv = *(const float4*)(wr + k);
                acc = fmaf(xv.x, wv.x, acc);
                acc = fmaf(xv.y, wv.y, acc);
                acc = fmaf(xv.z, wv.z, acc);
                acc = fmaf(xv.w, wv.w, acc);
            }
            g_R[v * 16 + j] = tanh_fast(acc);
        }
    } else {
        // ---------------- zero role: s0, s1, s2 ----------------
        const int n4 = (V * 16) / 4;
        const int stride = NZB * 256;
        float4 z = make_float4(0.f, 0.f, 0.f, 0.f);
        for (int i = (bid - 2 * NG) * 256 + tid; i < n4; i += stride) {
            ((float4*)g_s0)[i] = z;
            ((float4*)g_s1)[i] = z;
            ((float4*)g_s2)[i] = z;
        }
    }
}

// ---------------------------------------------------------------------------
// Step 1 (states=0 => H=R[src]): scatter-add R[src] into s0.
// 4 threads/edge, float4 load + red.global.add.v4.
// ---------------------------------------------------------------------------
static __global__ void k_prop_first(const int* __restrict__ Xn,
                                    const int* __restrict__ Xe, int E) {
    int idx = blockIdx.x * blockDim.x + threadIdx.x;
    if (idx >= E * 4) return;
    int e = idx >> 2, sq = (idx & 3) * 4;
    int src = __ldg(&Xn[e]);
    int nbr = __ldg(&Xe[e]);
    float4 r = __ldg((const float4*)(g_R + src * 16 + sq));
    float* dst = g_s0 + nbr * 16 + sq;
    asm volatile("red.global.add.v4.f32 [%0], {%1,%2,%3,%4};"
                 :: "l"(dst), "f"(r.x), "f"(r.y), "f"(r.z), "f"(r.w) : "memory");
}

// ---------------------------------------------------------------------------
// Fused prop step: A_e recomputed from fp8 P/Q (L2-resident).
// sel=0: s0 -> s1; sel=1: s1 -> s2.
// ---------------------------------------------------------------------------
static __global__ __launch_bounds__(256, 6)
void k_prop_fused(const int* __restrict__ Xn, const int* __restrict__ Xe,
                  const int* __restrict__ dg, int sel, int E)
{
    const float* in  = sel ? g_s1 : g_s0;
    float*       out = sel ? g_s2 : g_s1;
    int idx = blockIdx.x * 256 + threadIdx.x;
    int e = idx >> 4, s = idx & 15;
    if (e >= E) return;

    const int src = __ldg(&Xn[e]);
    const int nbr = __ldg(&Xe[e]);

    // 16 fp8 of P row + 16 of Q row: one uint4 each.
    const uint4 pu = __ldg((const uint4*)(g_P8 + (size_t)src * 256 + s * 16));
    const uint4 qu = __ldg((const uint4*)(g_Q8 + (size_t)nbr * 256 + s * 16));
    const float h   = __ldg(&in[src * 16 + s]);
    const float rsv = __ldg(&g_R[src * 16 + s]);
    const float sc  = __fdividef(0.05625f, (float)__ldg(&dg[e]));

    u64t hp[8];
    #pragma unroll
    for (int j = 0; j < 8; ++j) {
        float ha = __shfl_sync(0xffffffffu, h, 2 * j,     16);
        float hb = __shfl_sync(0xffffffffu, h, 2 * j + 1, 16);
        hp[j] = pack2(ha, hb);
    }

    const uint32_t pw[4] = { pu.x, pu.y, pu.z, pu.w };
    const uint32_t qw[4] = { qu.x, qu.y, qu.z, qu.w };
    __half2 sv[8];
    #pragma unroll
    for (int w = 0; w < 4; ++w) {
        sv[2 * w]     = __hadd2(fp8x2_to_h2((unsigned short)(pw[w] & 0xFFFFu)),
                                fp8x2_to_h2((unsigned short)(qw[w] & 0xFFFFu)));
        sv[2 * w + 1] = __hadd2(fp8x2_to_h2((unsigned short)(pw[w] >> 16)),
                                fp8x2_to_h2((unsigned short)(qw[w] >> 16)));
    }

    __half2 m = __habs2(sv[0]);
    #pragma unroll
    for (int j = 1; j < 8; ++j) m = __hmax2(m, __habs2(sv[j]));
    const float mx = fmaxf(__low2float(m), __high2float(m));

    u64t acc2 = 0ull;
    if (__builtin_expect(mx <= 0.6f, 1)) {
        const u64t c3 = pack2(-5.3968254e-2f, -5.3968254e-2f);
        const u64t c2 = pack2( 1.3333334e-1f,  1.3333334e-1f);
        const u64t c1 = pack2(-3.3333334e-1f, -3.3333334e-1f);
        const u64t c0 = pack2( 1.0f, 1.0f);
        #pragma unroll
        for (int j = 0; j < 8; ++j) {
            float2 f = __half22float2(sv[j]);
            u64t x = pack2(f.x, f.y);
            u64t t = mul2(x, x);
            u64t p = fma2(c3, t, c2);
            p = fma2(p, t, c1);
            p = fma2(p, t, c0);
            fma2_acc(acc2, mul2(x, p), hp[j]);
        }
    } else {
        #pragma unroll
        for (int j = 0; j < 8; ++j) {
            float2 f = __half22float2(sv[j]);
            fma2_acc(acc2, pack2(tanhf(f.x), tanhf(f.y)), hp[j]);
        }
    }

    float ra, rb2;
    unpack2(acc2, ra, rb2);
    float res = fmaf(sc, ra + rb2, rsv);
    atomicAdd(&out[nbr * 16 + s], res);
}

// ---------------------------------------------------------------------------
// Readout: logits = concat(emb, s2) @ lin_w + lin_b, softmax.  Warp/node.
// ---------------------------------------------------------------------------
static __global__ __launch_bounds__(256)
void k_final(const float* __restrict__ emb, const float* __restrict__ lw,
             const float* __restrict__ lb, float* __restrict__ out, int V)
{
    int v = (blockIdx.x * blockDim.x + threadIdx.x) >> 5;
    int lane = threadIdx.x & 31;
    if (v >= V) return;
    float p0 = 0.f, p1 = 0.f, p2 = 0.f;
    #pragma unroll
    for (int m = 0; m < 4; ++m) {
        int row = lane + 32 * m;
        float f = __ldg(&emb[(size_t)v * 128 + row]);
        p0 = fmaf(f, __ldg(&lw[row * 3 + 0]), p0);
        p1 = fmaf(f, __ldg(&lw[row * 3 + 1]), p1);
        p2 = fmaf(f, __ldg(&lw[row * 3 + 2]), p2);
    }
    if (lane < 16) {
        float sv = g_s2[v * 16 + lane];
        int row = 128 + lane;
        p0 = fmaf(sv, __ldg(&lw[row * 3 + 0]), p0);
        p1 = fmaf(sv, __ldg(&lw[row * 3 + 1]), p1);
        p2 = fmaf(sv, __ldg(&lw[row * 3 + 2]), p2);
    }
    #pragma unroll
    for (int off = 16; off > 0; off >>= 1) {
        p0 += __shfl_xor_sync(0xffffffffu, p0, off);
        p1 += __shfl_xor_sync(0xffffffffu, p1, off);
        p2 += __shfl_xor_sync(0xffffffffu, p2, off);
    }
    if (lane == 0) {
        p0 += __ldg(&lb[0]); p1 += __ldg(&lb[1]); p2 += __ldg(&lb[2]);
        float mx = fmaxf(p0, fmaxf(p1, p2));
        float e0 = expf(p0 - mx), e1 = expf(p1 - mx), e2 = expf(p2 - mx);
        float inv = 1.f / (e0 + e1 + e2);
        out[(size_t)v * 3 + 0] = e0 * inv;
        out[(size_t)v * 3 + 1] = e1 * inv;
        out[(size_t)v * 3 + 2] = e2 * inv;
    }
}

// ---------------------------------------------------------------------------
extern "C" void kernel_launch(void* const* d_in, const int* in_sizes, int n_in,
                              void* d_out, int out_size)
{
    const int*   X_Node = (const int*)  d_in[0];
    const int*   X_Neis = (const int*)  d_in[1];
    const int*   dg     = (const int*)  d_in[2];
    const float* emb    = (const float*)d_in[3];
    const float* xi_w   = (const float*)d_in[4];
    const float* xi_b   = (const float*)d_in[5];
    const float* rou_w  = (const float*)d_in[6];
    const float* rou_b  = (const float*)d_in[7];
    const float* lin_w  = (const float*)d_in[8];
    const float* lin_b  = (const float*)d_in[9];
    float* out = (float*)d_out;
    const int E = in_sizes[0];
    const int V = in_sizes[3] / 128;

    const int NG = (V + 63) / 64;
    const int pb = (E * 16 + 255) / 256;
    const int np = (V * 64 + 16384 + 255) / 256;

    // Prep: fp16 emb + fragment-ordered fp16 xi_w.
    k_prep<<<np, 256>>>(emb, xi_w, V);
    // K1: tensor-core node GEMM (P/Q fp8) + R table + zero s0/s1/s2.
    k_pre<<<2 * NG + NZB, 256>>>(emb, xi_b, rou_w, rou_b, V, NG);
    // step 1 (states=0 => H=R[src]): scatter into s0 (v4 reductions)
    k_prop_first<<<(E * 4 + 255) / 256, 256>>>(X_Node, X_Neis, E);
    // step 2: s0 -> s1 ; step 3: s1 -> s2  (fused A recompute, fp8 P/Q)
    k_prop_fused<<<pb, 256>>>(X_Node, X_Neis, dg, 0, E);
    k_prop_fused<<<pb, 256>>>(X_Node, X_Neis, dg, 1, E);
    // readout from s2
    k_final<<<(V + 7) / 8, 256>>>(emb, lin_w, lin_b, out, V);
}